// round 4
// baseline (speedup 1.0000x reference)
#include <cuda_runtime.h>
#include <cuda_fp16.h>
#include <math.h>

#define DIM 512
#define HID 2048
#define NLAYERS 4
#define VOCAB 32000
#define BB 2
#define SS 2048
#define M_TOT (BB*SS)   // 4096

// ---------------- scratch (device globals; no allocation allowed) ----------------
// fp32
__device__ float g_x [M_TOT*DIM];
__device__ float g_q [M_TOT*DIM];
__device__ float g_g [M_TOT*DIM];
__device__ float g_a [M_TOT*HID];
__device__ float g_nl[M_TOT];
__device__ float g_nlmax[M_TOT/64];
// packed split-fp16 (1 u32 per element: hi/lo pairs interleaved per 16-k chunk)
__device__ unsigned g_h_p [M_TOT*DIM];
__device__ unsigned g_f_p [M_TOT*DIM];
__device__ unsigned g_ao_p[M_TOT*DIM];
__device__ unsigned g_t_p [M_TOT*HID];
__device__ unsigned g_wq_p  [NLAYERS*DIM*DIM];
__device__ unsigned g_wg_p  [NLAYERS*DIM*DIM];
__device__ unsigned g_wout_p[NLAYERS*DIM*DIM];
__device__ unsigned g_whh_p [NLAYERS*HID*DIM];
__device__ unsigned g_wgg_p [NLAYERS*HID*DIM];
__device__ unsigned g_wo_p  [NLAYERS*DIM*HID];
// packed plain-fp16 (0.5 u32 per element)
__device__ unsigned g_hf_p [M_TOT*DIM/2];
__device__ unsigned g_emb_p[VOCAB*DIM/2];

__device__ __forceinline__ float silu_f(float v) {
    return v / (1.0f + __expf(-v));
}

__device__ __forceinline__ unsigned hpack(__half a, __half b) {
    __half2 t = __halves2half2(a, b);
    return *reinterpret_cast<unsigned*>(&t);
}

// split a pair of fp32 into (hi-halves packed, lo-halves packed)
__device__ __forceinline__ uint2 split2(float x0, float x1) {
    __half h0 = __float2half_rn(x0), h1 = __float2half_rn(x1);
    unsigned H = hpack(h0, h1);
    unsigned L = hpack(__float2half_rn(x0 - __half2float(h0)),
                       __float2half_rn(x1 - __half2float(h1)));
    return make_uint2(H, L);
}

// fp16 tensor-core mma, fp32 accumulate
__device__ __forceinline__ void mma_f16(float* c, const unsigned* a, const unsigned* b) {
    asm volatile(
        "mma.sync.aligned.m16n8k16.row.col.f32.f16.f16.f32 "
        "{%0,%1,%2,%3}, {%4,%5,%6,%7}, {%8,%9}, {%0,%1,%2,%3};"
        : "+f"(c[0]), "+f"(c[1]), "+f"(c[2]), "+f"(c[3])
        : "r"(a[0]), "r"(a[1]), "r"(a[2]), "r"(a[3]), "r"(b[0]), "r"(b[1]));
}

__device__ __forceinline__ void cp16(unsigned* dst, const unsigned* src) {
    unsigned d = (unsigned)__cvta_generic_to_shared(dst);
    asm volatile("cp.async.cg.shared.global [%0], [%1], 16;" :: "r"(d), "l"(src) : "memory");
}
#define CPA_COMMIT asm volatile("cp.async.commit_group;" ::: "memory")
#define CPA_WAIT1  asm volatile("cp.async.wait_group 1;" ::: "memory")

// layout helpers: within a 16-k chunk, pair p (k=2p,2p+1).
// split: uint2(H,L) at u32 offset (p&3)*4 + ((p>>2)<<1)   (16 u32/chunk/row)
// plain: H at u32 offset (p&3)*2 + (p>>2)                  (8 u32/chunk/row)
__device__ __forceinline__ int spos(int p) { return (p & 3) * 4 + ((p >> 2) << 1); }
__device__ __forceinline__ int ppos(int p) { return (p & 3) * 2 + (p >> 2); }

// ---------------- weight conversion (fp32 -> packed) ----------------
__global__ void convert_split(const float* __restrict__ src, unsigned* __restrict__ dst,
                              long total4, int K) {
    long idx = (long)blockIdx.x * 256 + threadIdx.x;
    if (idx >= total4) return;
    int perRow = K >> 2;
    long row = idx / perRow;
    int rem = (int)(idx - row * perRow);
    int kc = rem >> 2, i4 = rem & 3;
    float4 v = reinterpret_cast<const float4*>(src)[idx];
    unsigned* base = dst + row * (long)K + kc * 16;
    int p0 = 2 * i4;
    *reinterpret_cast<uint2*>(base + spos(p0))     = split2(v.x, v.y);
    *reinterpret_cast<uint2*>(base + spos(p0 + 1)) = split2(v.z, v.w);
}

__global__ void convert_plain(const float* __restrict__ src, unsigned* __restrict__ dst,
                              long total4, int K) {
    long idx = (long)blockIdx.x * 256 + threadIdx.x;
    if (idx >= total4) return;
    int perRow = K >> 2;
    long row = idx / perRow;
    int rem = (int)(idx - row * perRow);
    int kc = rem >> 2, i4 = rem & 3;
    float4 v = reinterpret_cast<const float4*>(src)[idx];
    unsigned* base = dst + row * (long)(K >> 1) + kc * 8;
    int p0 = 2 * i4;
    base[ppos(p0)]     = hpack(__float2half_rn(v.x), __float2half_rn(v.y));
    base[ppos(p0 + 1)] = hpack(__float2half_rn(v.z), __float2half_rn(v.w));
}

// ---------------- embedding gather ----------------
__global__ void embed_kernel(const int* __restrict__ tok,
                             const float* __restrict__ emb,
                             float* __restrict__ X) {
    long idx = (long)blockIdx.x * 256 + threadIdx.x;
    int row = (int)(idx >> 7);
    int c   = (int)(idx & 127);
    int t   = tok[row];
    reinterpret_cast<float4*>(X)[idx] =
        reinterpret_cast<const float4*>(emb + (long)t * DIM)[c];
}

// ---------------- RMSNorm -> packed output (+ optional lambda -> log_sigmoid) -------
// PACK: 0 split, 1 plain
template<bool LAM, int PACK>
__global__ void rmsnorm_kernel(const float* __restrict__ X,
                               const float* __restrict__ w,
                               const float* __restrict__ lam,
                               unsigned* __restrict__ Hp,
                               float* __restrict__ NL) {
    __shared__ float sb[4];
    __shared__ float s_scale;
    const int row = blockIdx.x;
    const int t = threadIdx.x;               // 128 threads, 4 floats each
    float4 v = reinterpret_cast<const float4*>(X + (long)row * DIM)[t];
    float ss = v.x*v.x + v.y*v.y + v.z*v.z + v.w*v.w;
    #pragma unroll
    for (int o = 16; o > 0; o >>= 1) ss += __shfl_down_sync(0xffffffffu, ss, o);
    if ((t & 31) == 0) sb[t >> 5] = ss;
    __syncthreads();
    if (t == 0) {
        float tot = sb[0] + sb[1] + sb[2] + sb[3];
        s_scale = rsqrtf(tot / (float)DIM + 1e-6f);
    }
    __syncthreads();
    const float sc = s_scale;
    float4 wv = reinterpret_cast<const float4*>(w)[t];
    float4 h;
    h.x = v.x * sc * wv.x;
    h.y = v.y * sc * wv.y;
    h.z = v.z * sc * wv.z;
    h.w = v.w * sc * wv.w;
    const int kc = t >> 2, i4 = t & 3;
    const int p0 = 2 * i4;
    if (PACK == 0) {
        unsigned* base = Hp + (long)row * DIM + kc * 16;
        *reinterpret_cast<uint2*>(base + spos(p0))     = split2(h.x, h.y);
        *reinterpret_cast<uint2*>(base + spos(p0 + 1)) = split2(h.z, h.w);
    } else {
        unsigned* base = Hp + (long)row * (DIM / 2) + kc * 8;
        base[ppos(p0)]     = hpack(__float2half_rn(h.x), __float2half_rn(h.y));
        base[ppos(p0 + 1)] = hpack(__float2half_rn(h.z), __float2half_rn(h.w));
    }
    if (LAM) {
        float4 lv = reinterpret_cast<const float4*>(lam)[t];
        float d = h.x*lv.x + h.y*lv.y + h.z*lv.z + h.w*lv.w;
        #pragma unroll
        for (int o = 16; o > 0; o >>= 1) d += __shfl_down_sync(0xffffffffu, d, o);
        __syncthreads();
        if ((t & 31) == 0) sb[t >> 5] = d;
        __syncthreads();
        if (t == 0) {
            float dot = sb[0] + sb[1] + sb[2] + sb[3];
            float nl = (dot >= 0.0f) ? -log1pf(expf(-dot))
                                     : (dot - log1pf(expf(dot)));
            NL[row] = nl;
        }
    }
}

// per-64-row-tile max of nl (for decay band pruning)
__global__ void nlmax_kernel(const float* __restrict__ NL, float* __restrict__ NM) {
    int base = blockIdx.x * 64;
    int lid = threadIdx.x;  // 32
    float v = fmaxf(NL[base + lid], NL[base + 32 + lid]);
    #pragma unroll
    for (int o = 16; o > 0; o >>= 1) v = fmaxf(v, __shfl_xor_sync(0xffffffffu, v, o));
    if (lid == 0) NM[blockIdx.x] = v;
}

// ---------------- tensor-core NT GEMM, cp.async 3-stage, packed inputs --------------
// A: [M,K] packed (split: K u32/row, plain: K/2 u32/row), W: [N,K] packed same mode.
// Tile 128 x NT, 32-k stages, 8 warps (warptile 64 x NT/4).
// EPI: 0 C=acc | 1 C+=acc | 2 C+=acc*E | 3 CP=packsplit(silu(acc)*E)
template<bool SPLIT, int NT, int EPI>
__global__ void __launch_bounds__(256) gemm_tc(
    const unsigned* __restrict__ A, const unsigned* __restrict__ W,
    float* __restrict__ C, const float* __restrict__ E,
    unsigned* __restrict__ CP, int M, int N, int K)
{
    constexpr int RS  = SPLIT ? 16 : 8;        // u32 per row per 16-k subchunk
    constexpr int ASZ = 128 * 2 * RS;          // u32 per stage (A)
    constexpr int BSZ = NT * 2 * RS;           // u32 per stage (B)
    constexpr int NI  = NT / 32;
    extern __shared__ unsigned sm[];

    const int tid  = threadIdx.x;
    const int lane = tid & 31;
    const int gr   = lane >> 2;
    const int tc   = lane & 3;
    const int warp = tid >> 5;
    const int wm   = warp >> 2;
    const int wn   = warp & 3;
    const long bm = (long)blockIdx.y * 128;
    const long bn = (long)blockIdx.x * NT;
    const long Ku = SPLIT ? K : (K >> 1);

    float acc[4][NI][4] = {};

    auto issue = [&](int s, int it) {
        unsigned* Sa = sm + s * (ASZ + BSZ);
        unsigned* Sb = Sa + ASZ;
        if (SPLIT) {
            int row = tid >> 1, half = tid & 1;
            const unsigned* src = A + (bm + row) * Ku + it * 32 + half * 16;
            unsigned* dst = Sa + half * (128 * 16) + row * 16;
            cp16(dst, src); cp16(dst + 4, src + 4);
            cp16(dst + 8, src + 8); cp16(dst + 12, src + 12);
            if (NT == 128) {
                const unsigned* sbp = W + (bn + row) * Ku + it * 32 + half * 16;
                unsigned* dbp = Sb + half * (128 * 16) + row * 16;
                cp16(dbp, sbp); cp16(dbp + 4, sbp + 4);
                cp16(dbp + 8, sbp + 8); cp16(dbp + 12, sbp + 12);
            } else {
                int rb = tid >> 2, qq = tid & 3, hb = qq >> 1, sg = (qq & 1) * 8;
                const unsigned* sbp = W + (bn + rb) * Ku + it * 32 + hb * 16 + sg;
                unsigned* dbp = Sb + hb * (64 * 16) + rb * 16 + sg;
                cp16(dbp, sbp); cp16(dbp + 4, sbp + 4);
            }
        } else {
            int row = tid >> 1, half = tid & 1;
            const unsigned* src = A + (bm + row) * Ku + it * 16 + half * 8;
            unsigned* dst = Sa + half * (128 * 8) + row * 8;
            cp16(dst, src); cp16(dst + 4, src + 4);
            const unsigned* sbp = W + (bn + row) * Ku + it * 16 + half * 8;
            unsigned* dbp = Sb + half * (128 * 8) + row * 8;
            cp16(dbp, sbp); cp16(dbp + 4, sbp + 4);
        }
    };

    const int nIter = K >> 5;                  // 32-k stages
    issue(0, 0); CPA_COMMIT;
    issue(1, 1); CPA_COMMIT;

    for (int it = 0; it < nIter; it++) {
        CPA_WAIT1;
        __syncthreads();
        if (it + 2 < nIter) issue((it + 2) % 3, it + 2);
        CPA_COMMIT;

        const unsigned* Sa = sm + (it % 3) * (ASZ + BSZ);
        const unsigned* Sb = Sa + ASZ;
        #pragma unroll
        for (int sc = 0; sc < 2; sc++) {
            const unsigned* Asc = Sa + sc * (128 * RS);
            const unsigned* Bsc = Sb + sc * (NT * RS);
            if (SPLIT) {
                unsigned bhi[NI][2], blo[NI][2];
                #pragma unroll
                for (int ni = 0; ni < NI; ni++) {
                    uint4 f = *reinterpret_cast<const uint4*>(
                        Bsc + (wn * (NT/4) + ni * 8 + gr) * 16 + tc * 4);
                    bhi[ni][0] = f.x; blo[ni][0] = f.y;
                    bhi[ni][1] = f.z; blo[ni][1] = f.w;
                }
                #pragma unroll
                for (int mi = 0; mi < 4; mi++) {
                    int r = wm * 64 + mi * 16 + gr;
                    uint4 f0 = *reinterpret_cast<const uint4*>(Asc + r * 16 + tc * 4);
                    uint4 f1 = *reinterpret_cast<const uint4*>(Asc + (r + 8) * 16 + tc * 4);
                    unsigned ahi[4] = {f0.x, f1.x, f0.z, f1.z};
                    unsigned alo[4] = {f0.y, f1.y, f0.w, f1.w};
                    #pragma unroll
                    for (int ni = 0; ni < NI; ni++) {
                        mma_f16(acc[mi][ni], ahi, bhi[ni]);
                        mma_f16(acc[mi][ni], alo, bhi[ni]);
                        mma_f16(acc[mi][ni], ahi, blo[ni]);
                    }
                }
            } else {
                unsigned bf[NI][2];
                #pragma unroll
                for (int ni = 0; ni < NI; ni++) {
                    uint2 f = *reinterpret_cast<const uint2*>(
                        Bsc + (wn * (NT/4) + ni * 8 + gr) * 8 + tc * 2);
                    bf[ni][0] = f.x; bf[ni][1] = f.y;
                }
                #pragma unroll
                for (int mi = 0; mi < 4; mi++) {
                    int r = wm * 64 + mi * 16 + gr;
                    uint2 f0 = *reinterpret_cast<const uint2*>(Asc + r * 8 + tc * 2);
                    uint2 f1 = *reinterpret_cast<const uint2*>(Asc + (r + 8) * 8 + tc * 2);
                    unsigned af[4] = {f0.x, f1.x, f0.y, f1.y};
                    #pragma unroll
                    for (int ni = 0; ni < NI; ni++)
                        mma_f16(acc[mi][ni], af, bf[ni]);
                }
            }
        }
    }

    // epilogue
    #pragma unroll
    for (int mi = 0; mi < 4; mi++) {
        #pragma unroll
        for (int ni = 0; ni < NI; ni++) {
            long row = bm + wm * 64 + mi * 16 + gr;
            int col = (int)bn + wn * (NT/4) + ni * 8 + tc * 2;
            float* a = acc[mi][ni];
            long i0 = row * (long)N + col;
            long i1 = (row + 8) * (long)N + col;
            if (EPI == 3) {
                float2 e0 = *reinterpret_cast<const float2*>(&E[i0]);
                float2 e1 = *reinterpret_cast<const float2*>(&E[i1]);
                uint2 w0 = split2(silu_f(a[0]) * e0.x, silu_f(a[1]) * e0.y);
                uint2 w1 = split2(silu_f(a[2]) * e1.x, silu_f(a[3]) * e1.y);
                int kc = col >> 4, p = (col >> 1) & 7;
                int pos = spos(p);
                *reinterpret_cast<uint2*>(CP + row * (long)N + kc * 16 + pos)       = w0;
                *reinterpret_cast<uint2*>(CP + (row + 8) * (long)N + kc * 16 + pos) = w1;
            } else {
                float2 o0, o1;
                if (EPI == 0) {
                    o0 = make_float2(a[0], a[1]);
                    o1 = make_float2(a[2], a[3]);
                } else if (EPI == 1) {
                    float2 c0 = *reinterpret_cast<float2*>(&C[i0]);
                    float2 c1 = *reinterpret_cast<float2*>(&C[i1]);
                    o0 = make_float2(c0.x + a[0], c0.y + a[1]);
                    o1 = make_float2(c1.x + a[2], c1.y + a[3]);
                } else {
                    float2 c0 = *reinterpret_cast<float2*>(&C[i0]);
                    float2 c1 = *reinterpret_cast<float2*>(&C[i1]);
                    float2 e0 = *reinterpret_cast<const float2*>(&E[i0]);
                    float2 e1 = *reinterpret_cast<const float2*>(&E[i1]);
                    o0 = make_float2(c0.x + a[0]*e0.x, c0.y + a[1]*e0.y);
                    o1 = make_float2(c1.x + a[2]*e1.x, c1.y + a[3]*e1.y);
                }
                *reinterpret_cast<float2*>(&C[i0]) = o0;
                *reinterpret_cast<float2*>(&C[i1]) = o1;
            }
        }
    }
}

// ---------------- decay attention with band pruning; emits packed silu(out) ---------
__global__ void __launch_bounds__(256) decay_attn(
    const float* __restrict__ Q, const float* __restrict__ NLv,
    const float* __restrict__ NM, unsigned* __restrict__ AOp)
{
    const int it = blockIdx.x;
    const int dt = blockIdx.y;
    const int b  = blockIdx.z;
    const float* q  = Q + (long)b*SS*DIM + dt*64;
    const float* nl = NLv + (long)b*SS;
    const float* nlmax = NM + b*(SS/64);
    __shared__ float qs[64][64];
    __shared__ float nls[64];
    __shared__ float sgs[64];
    const int tid = threadIdx.x;
    const int tx = tid & 15, ty = tid >> 4;
    float acc[4][4] = {};
    const int i0 = it*64 + ty*4;

    for (int jt = 0; jt <= it; jt++) {
        if (jt < it) {
            float dmin = (float)(it*64 - (jt*64 + 63));
            if (nlmax[jt] * dmin < -40.0f) continue;
        }
        {
            int r = tid >> 4;
            int c = (tid & 15) * 4;
            #pragma unroll
            for (int rr = 0; rr < 64; rr += 16) {
                float4 v = *reinterpret_cast<const float4*>(
                    q + (long)(jt*64 + r + rr) * DIM + c);
                *reinterpret_cast<float4*>(&qs[r + rr][c]) = v;
            }
        }
        if (tid < 64) {
            float xv = nl[jt*64 + tid];
            nls[tid] = xv;
            sgs[tid] = expf(xv);
        }
        __syncthreads();

        if (jt < it) {
            #pragma unroll 2
            for (int j = 0; j < 64; j++) {
                float s = sgs[j];
                float w = expf(nls[j] * (float)(i0 - (jt*64 + j)));
                float4 qv = *reinterpret_cast<const float4*>(&qs[j][tx*4]);
                #pragma unroll
                for (int ii = 0; ii < 4; ii++) {
                    acc[ii][0] += w * qv.x;
                    acc[ii][1] += w * qv.y;
                    acc[ii][2] += w * qv.z;
                    acc[ii][3] += w * qv.w;
                    w *= s;
                }
            }
        } else {
            for (int j = 0; j < 64; j++) {
                int jg = jt*64 + j;
                float4 qv = *reinterpret_cast<const float4*>(&qs[j][tx*4]);
                #pragma unroll
                for (int ii = 0; ii < 4; ii++) {
                    int d = i0 + ii - jg;
                    float w = (d >= 0) ? expf(nls[j] * (float)d) : 0.0f;
                    acc[ii][0] += w * qv.x;
                    acc[ii][1] += w * qv.y;
                    acc[ii][2] += w * qv.z;
                    acc[ii][3] += w * qv.w;
                }
            }
        }
        __syncthreads();
    }

    // write packed split-fp16 silu(out) in GEMM A layout
    const int kc = dt * 4 + (tx >> 2);
    const int p0 = 2 * (tx & 3);
    const int pos0 = spos(p0), pos1 = spos(p0 + 1);
    #pragma unroll
    for (int ii = 0; ii < 4; ii++) {
        long r = (long)b * SS + i0 + ii;
        uint2 w0 = split2(silu_f(acc[ii][0]), silu_f(acc[ii][1]));
        uint2 w1 = split2(silu_f(acc[ii][2]), silu_f(acc[ii][3]));
        unsigned* base = AOp + r * DIM + kc * 16;
        *reinterpret_cast<uint2*>(base + pos0) = w0;
        *reinterpret_cast<uint2*>(base + pos1) = w1;
    }
}

// ---------------- orchestration ----------------
extern "C" void kernel_launch(void* const* d_in, const int* in_sizes, int n_in,
                              void* d_out, int out_size) {
    const int*   tokens       = (const int*)  d_in[0];
    const float* emb          = (const float*)d_in[1];
    const float* decay_norm_w = (const float*)d_in[2];
    const float* lambda_w     = (const float*)d_in[3];
    const float* quantity_w   = (const float*)d_in[4];
    const float* gate_w       = (const float*)d_in[5];
    const float* output_w     = (const float*)d_in[6];
    const float* ffn_norm_w   = (const float*)d_in[7];
    const float* w_h          = (const float*)d_in[8];
    const float* w_g          = (const float*)d_in[9];
    const float* w_o          = (const float*)d_in[10];
    const float* out_norm_w   = (const float*)d_in[11];
    float* out = (float*)d_out;

    float *x, *q, *g, *a, *nl, *nm;
    unsigned *h_p, *f_p, *ao_p, *t_p, *hf_p, *emb_p;
    unsigned *wq_p, *wg_p, *wout_p, *whh_p, *wgg_p, *wo_p;
    cudaGetSymbolAddress((void**)&x,  g_x);
    cudaGetSymbolAddress((void**)&q,  g_q);
    cudaGetSymbolAddress((void**)&g,  g_g);
    cudaGetSymbolAddress((void**)&a,  g_a);
    cudaGetSymbolAddress((void**)&nl, g_nl);
    cudaGetSymbolAddress((void**)&nm, g_nlmax);
    cudaGetSymbolAddress((void**)&h_p,  g_h_p);
    cudaGetSymbolAddress((void**)&f_p,  g_f_p);
    cudaGetSymbolAddress((void**)&ao_p, g_ao_p);
    cudaGetSymbolAddress((void**)&t_p,  g_t_p);
    cudaGetSymbolAddress((void**)&hf_p, g_hf_p);
    cudaGetSymbolAddress((void**)&emb_p,g_emb_p);
    cudaGetSymbolAddress((void**)&wq_p,  g_wq_p);
    cudaGetSymbolAddress((void**)&wg_p,  g_wg_p);
    cudaGetSymbolAddress((void**)&wout_p,g_wout_p);
    cudaGetSymbolAddress((void**)&whh_p, g_whh_p);
    cudaGetSymbolAddress((void**)&wgg_p, g_wgg_p);
    cudaGetSymbolAddress((void**)&wo_p,  g_wo_p);

    // opt-in dynamic smem sizes
    const int SM_S128 = 3 * (128*32 + 128*32) * 4;   // 98304
    const int SM_S64  = 3 * (128*32 +  64*32) * 4;   // 73728
    const int SM_P128 = 3 * (128*16 + 128*16) * 4;   // 49152
    cudaFuncSetAttribute(gemm_tc<true,64,0>,  cudaFuncAttributeMaxDynamicSharedMemorySize, SM_S64);
    cudaFuncSetAttribute(gemm_tc<true,64,1>,  cudaFuncAttributeMaxDynamicSharedMemorySize, SM_S64);
    cudaFuncSetAttribute(gemm_tc<true,64,2>,  cudaFuncAttributeMaxDynamicSharedMemorySize, SM_S64);
    cudaFuncSetAttribute(gemm_tc<true,128,0>, cudaFuncAttributeMaxDynamicSharedMemorySize, SM_S128);
    cudaFuncSetAttribute(gemm_tc<true,128,3>, cudaFuncAttributeMaxDynamicSharedMemorySize, SM_S128);
    cudaFuncSetAttribute(gemm_tc<false,128,0>,cudaFuncAttributeMaxDynamicSharedMemorySize, SM_P128);

    // one-time weight conversions (per forward)
    {
        long t4;
        t4 = (long)NLAYERS*DIM*DIM/4;
        convert_split<<<(unsigned)((t4+255)/256), 256>>>(quantity_w, wq_p,  t4, DIM);
        convert_split<<<(unsigned)((t4+255)/256), 256>>>(gate_w,     wg_p,  t4, DIM);
        convert_split<<<(unsigned)((t4+255)/256), 256>>>(output_w,   wout_p,t4, DIM);
        t4 = (long)NLAYERS*HID*DIM/4;
        convert_split<<<(unsigned)((t4+255)/256), 256>>>(w_h, whh_p, t4, DIM);
        convert_split<<<(unsigned)((t4+255)/256), 256>>>(w_g, wgg_p, t4, DIM);
        convert_split<<<(unsigned)((t4+255)/256), 256>>>(w_o, wo_p,  t4, HID);
        t4 = (long)VOCAB*DIM/4;
        convert_plain<<<(unsigned)((t4+255)/256), 256>>>(emb, emb_p, t4, DIM);
    }

    embed_kernel<<<M_TOT * (DIM/4) / 256, 256>>>(tokens, emb, x);

    dim3 g512 (DIM/64,    M_TOT/128);   // (8,  32) NT=64
    dim3 g2048(HID/128,   M_TOT/128);   // (16, 32) NT=128
    dim3 gV   (VOCAB/128, M_TOT/128);   // (250,32) NT=128
    dim3 gattn(SS/64, DIM/64, BB);

    for (int l = 0; l < NLAYERS; l++) {
        rmsnorm_kernel<true,0><<<M_TOT, 128>>>(x, decay_norm_w + l*DIM,
                                               lambda_w + l*DIM, h_p, nl);
        nlmax_kernel<<<M_TOT/64, 32>>>(nl, nm);
        gemm_tc<true,64,0><<<g512, 256, SM_S64>>>(h_p, wq_p + (long)l*DIM*DIM, q,
                                                  nullptr, nullptr, M_TOT, DIM, DIM);
        gemm_tc<true,64,0><<<g512, 256, SM_S64>>>(h_p, wg_p + (long)l*DIM*DIM, g,
                                                  nullptr, nullptr, M_TOT, DIM, DIM);
        decay_attn<<<gattn, 256>>>(q, nl, nm, ao_p);
        // x += (silu(ao) @ Wout^T) * g    (silu already folded into ao_p)
        gemm_tc<true,64,2><<<g512, 256, SM_S64>>>(ao_p, wout_p + (long)l*DIM*DIM, x,
                                                  g, nullptr, M_TOT, DIM, DIM);
        rmsnorm_kernel<false,0><<<M_TOT, 128>>>(x, ffn_norm_w + l*DIM,
                                                nullptr, f_p, nullptr);
        gemm_tc<true,128,0><<<g2048, 256, SM_S128>>>(f_p, whh_p + (long)l*HID*DIM, a,
                                                     nullptr, nullptr, M_TOT, HID, DIM);
        // t = silu(f@Wg^T) * a  (packed split output)
        gemm_tc<true,128,3><<<g2048, 256, SM_S128>>>(f_p, wgg_p + (long)l*HID*DIM, nullptr,
                                                     a, t_p, M_TOT, HID, DIM);
        gemm_tc<true,64,1><<<g512, 256, SM_S64>>>(t_p, wo_p + (long)l*DIM*HID, x,
                                                  nullptr, nullptr, M_TOT, DIM, HID);
    }

    rmsnorm_kernel<false,1><<<M_TOT, 128>>>(x, out_norm_w, nullptr, hf_p, nullptr);
    gemm_tc<false,128,0><<<gV, 256, SM_P128>>>(hf_p, emb_p, out, nullptr, nullptr,
                                               M_TOT, VOCAB, DIM);
}

// round 5
// speedup vs baseline: 1.0185x; 1.0185x over previous
#include <cuda_runtime.h>
#include <cuda_fp16.h>
#include <math.h>

#define DIM 512
#define HID 2048
#define NLAYERS 4
#define VOCAB 32000
#define BB 2
#define SS 2048
#define M_TOT (BB*SS)   // 4096

// ---------------- scratch (device globals; no allocation allowed) ----------------
__device__ float g_x [M_TOT*DIM];
__device__ float g_q [M_TOT*DIM];
__device__ float g_g [M_TOT*DIM];
__device__ float g_a [M_TOT*HID];
__device__ float g_nl[M_TOT];
__device__ float g_nlmax[M_TOT/64];
// packed split-fp16 (1 u32 per element)
__device__ unsigned g_h_p [M_TOT*DIM];
__device__ unsigned g_f_p [M_TOT*DIM];
__device__ unsigned g_ao_p[M_TOT*DIM];
__device__ unsigned g_t_p [M_TOT*HID];
__device__ unsigned g_wq_p  [NLAYERS*DIM*DIM];
__device__ unsigned g_wg_p  [NLAYERS*DIM*DIM];
__device__ unsigned g_wout_p[NLAYERS*DIM*DIM];
__device__ unsigned g_whh_p [NLAYERS*HID*DIM];
__device__ unsigned g_wgg_p [NLAYERS*HID*DIM];
__device__ unsigned g_wo_p  [NLAYERS*DIM*HID];
// packed plain-fp16 (0.5 u32 per element)
__device__ unsigned g_hf_p [M_TOT*DIM/2];
__device__ unsigned g_emb_p[VOCAB*DIM/2];

__device__ __forceinline__ float silu_f(float v) {
    return v / (1.0f + __expf(-v));
}

__device__ __forceinline__ unsigned hpack(__half a, __half b) {
    __half2 t = __halves2half2(a, b);
    return *reinterpret_cast<unsigned*>(&t);
}

__device__ __forceinline__ uint2 split2(float x0, float x1) {
    __half h0 = __float2half_rn(x0), h1 = __float2half_rn(x1);
    unsigned H = hpack(h0, h1);
    unsigned L = hpack(__float2half_rn(x0 - __half2float(h0)),
                       __float2half_rn(x1 - __half2float(h1)));
    return make_uint2(H, L);
}

__device__ __forceinline__ void mma_f16(float* c, const unsigned* a, const unsigned* b) {
    asm volatile(
        "mma.sync.aligned.m16n8k16.row.col.f32.f16.f16.f32 "
        "{%0,%1,%2,%3}, {%4,%5,%6,%7}, {%8,%9}, {%0,%1,%2,%3};"
        : "+f"(c[0]), "+f"(c[1]), "+f"(c[2]), "+f"(c[3])
        : "r"(a[0]), "r"(a[1]), "r"(a[2]), "r"(a[3]), "r"(b[0]), "r"(b[1]));
}

__device__ __forceinline__ void cp16(unsigned* dst, const unsigned* src) {
    unsigned d = (unsigned)__cvta_generic_to_shared(dst);
    asm volatile("cp.async.cg.shared.global [%0], [%1], 16;" :: "r"(d), "l"(src) : "memory");
}
#define CPA_COMMIT asm volatile("cp.async.commit_group;" ::: "memory")
#define CPA_WAIT1  asm volatile("cp.async.wait_group 1;" ::: "memory")

// layout helpers: within a 16-k chunk, pair p (k=2p,2p+1)
__device__ __forceinline__ int spos(int p) { return (p & 3) * 4 + ((p >> 2) << 1); }
__device__ __forceinline__ int ppos(int p) { return (p & 3) * 2 + (p >> 2); }

// ---------------- weight conversion (fp32 -> packed) ----------------
__global__ void convert_split(const float* __restrict__ src, unsigned* __restrict__ dst,
                              long total4, int K) {
    long idx = (long)blockIdx.x * 256 + threadIdx.x;
    if (idx >= total4) return;
    int perRow = K >> 2;
    long row = idx / perRow;
    int rem = (int)(idx - row * perRow);
    int kc = rem >> 2, i4 = rem & 3;
    float4 v = reinterpret_cast<const float4*>(src)[idx];
    unsigned* base = dst + row * (long)K + kc * 16;
    int p0 = 2 * i4;
    *reinterpret_cast<uint2*>(base + spos(p0))     = split2(v.x, v.y);
    *reinterpret_cast<uint2*>(base + spos(p0 + 1)) = split2(v.z, v.w);
}

__global__ void convert_plain(const float* __restrict__ src, unsigned* __restrict__ dst,
                              long total4, int K) {
    long idx = (long)blockIdx.x * 256 + threadIdx.x;
    if (idx >= total4) return;
    int perRow = K >> 2;
    long row = idx / perRow;
    int rem = (int)(idx - row * perRow);
    int kc = rem >> 2, i4 = rem & 3;
    float4 v = reinterpret_cast<const float4*>(src)[idx];
    unsigned* base = dst + row * (long)(K >> 1) + kc * 8;
    int p0 = 2 * i4;
    base[ppos(p0)]     = hpack(__float2half_rn(v.x), __float2half_rn(v.y));
    base[ppos(p0 + 1)] = hpack(__float2half_rn(v.z), __float2half_rn(v.w));
}

// ---------------- embedding gather ----------------
__global__ void embed_kernel(const int* __restrict__ tok,
                             const float* __restrict__ emb,
                             float* __restrict__ X) {
    long idx = (long)blockIdx.x * 256 + threadIdx.x;
    int row = (int)(idx >> 7);
    int c   = (int)(idx & 127);
    int t   = tok[row];
    reinterpret_cast<float4*>(X)[idx] =
        reinterpret_cast<const float4*>(emb + (long)t * DIM)[c];
}

// ---------------- RMSNorm -> packed output ----------------
template<bool LAM, int PACK>
__global__ void rmsnorm_kernel(const float* __restrict__ X,
                               const float* __restrict__ w,
                               const float* __restrict__ lam,
                               unsigned* __restrict__ Hp,
                               float* __restrict__ NL) {
    __shared__ float sb[4];
    __shared__ float s_scale;
    const int row = blockIdx.x;
    const int t = threadIdx.x;
    float4 v = reinterpret_cast<const float4*>(X + (long)row * DIM)[t];
    float ss = v.x*v.x + v.y*v.y + v.z*v.z + v.w*v.w;
    #pragma unroll
    for (int o = 16; o > 0; o >>= 1) ss += __shfl_down_sync(0xffffffffu, ss, o);
    if ((t & 31) == 0) sb[t >> 5] = ss;
    __syncthreads();
    if (t == 0) {
        float tot = sb[0] + sb[1] + sb[2] + sb[3];
        s_scale = rsqrtf(tot / (float)DIM + 1e-6f);
    }
    __syncthreads();
    const float sc = s_scale;
    float4 wv = reinterpret_cast<const float4*>(w)[t];
    float4 h;
    h.x = v.x * sc * wv.x;
    h.y = v.y * sc * wv.y;
    h.z = v.z * sc * wv.z;
    h.w = v.w * sc * wv.w;
    const int kc = t >> 2, i4 = t & 3;
    const int p0 = 2 * i4;
    if (PACK == 0) {
        unsigned* base = Hp + (long)row * DIM + kc * 16;
        *reinterpret_cast<uint2*>(base + spos(p0))     = split2(h.x, h.y);
        *reinterpret_cast<uint2*>(base + spos(p0 + 1)) = split2(h.z, h.w);
    } else {
        unsigned* base = Hp + (long)row * (DIM / 2) + kc * 8;
        base[ppos(p0)]     = hpack(__float2half_rn(h.x), __float2half_rn(h.y));
        base[ppos(p0 + 1)] = hpack(__float2half_rn(h.z), __float2half_rn(h.w));
    }
    if (LAM) {
        float4 lv = reinterpret_cast<const float4*>(lam)[t];
        float d = h.x*lv.x + h.y*lv.y + h.z*lv.z + h.w*lv.w;
        #pragma unroll
        for (int o = 16; o > 0; o >>= 1) d += __shfl_down_sync(0xffffffffu, d, o);
        __syncthreads();
        if ((t & 31) == 0) sb[t >> 5] = d;
        __syncthreads();
        if (t == 0) {
            float dot = sb[0] + sb[1] + sb[2] + sb[3];
            float nl = (dot >= 0.0f) ? -log1pf(expf(-dot))
                                     : (dot - log1pf(expf(dot)));
            NL[row] = nl;
        }
    }
}

__global__ void nlmax_kernel(const float* __restrict__ NL, float* __restrict__ NM) {
    int base = blockIdx.x * 64;
    int lid = threadIdx.x;
    float v = fmaxf(NL[base + lid], NL[base + 32 + lid]);
    #pragma unroll
    for (int o = 16; o > 0; o >>= 1) v = fmaxf(v, __shfl_xor_sync(0xffffffffu, v, o));
    if (lid == 0) NM[blockIdx.x] = v;
}

// ---------------- tensor-core NT GEMM, cp.async 3-stage, packed inputs --------------
// Pass-ordered mmas (all hi*hi, then hi*lo, then lo*hi) for ILP; 2 CTAs/SM.
// EPI: 0 C=acc | 1 C+=acc | 2 C+=acc*E | 3 CP=packsplit(silu(acc)*E)
template<bool SPLIT, int NT, int EPI>
__global__ void __launch_bounds__(256, 2) gemm_tc(
    const unsigned* __restrict__ A, const unsigned* __restrict__ W,
    float* __restrict__ C, const float* __restrict__ E,
    unsigned* __restrict__ CP, int M, int N, int K)
{
    constexpr int RS  = SPLIT ? 16 : 8;
    constexpr int ASZ = 128 * 2 * RS;
    constexpr int BSZ = NT * 2 * RS;
    constexpr int NI  = NT / 32;
    extern __shared__ unsigned sm[];

    const int tid  = threadIdx.x;
    const int lane = tid & 31;
    const int gr   = lane >> 2;
    const int tc   = lane & 3;
    const int warp = tid >> 5;
    const int wm   = warp >> 2;
    const int wn   = warp & 3;
    const long bm = (long)blockIdx.y * 128;
    const long bn = (long)blockIdx.x * NT;
    const long Ku = SPLIT ? K : (K >> 1);

    float acc[4][NI][4] = {};

    auto issue = [&](int s, int it) {
        unsigned* Sa = sm + s * (ASZ + BSZ);
        unsigned* Sb = Sa + ASZ;
        if (SPLIT) {
            int row = tid >> 1, half = tid & 1;
            const unsigned* src = A + (bm + row) * Ku + it * 32 + half * 16;
            unsigned* dst = Sa + half * (128 * 16) + row * 16;
            cp16(dst, src); cp16(dst + 4, src + 4);
            cp16(dst + 8, src + 8); cp16(dst + 12, src + 12);
            if (NT == 128) {
                const unsigned* sbp = W + (bn + row) * Ku + it * 32 + half * 16;
                unsigned* dbp = Sb + half * (128 * 16) + row * 16;
                cp16(dbp, sbp); cp16(dbp + 4, sbp + 4);
                cp16(dbp + 8, sbp + 8); cp16(dbp + 12, sbp + 12);
            } else {
                int rb = tid >> 2, qq = tid & 3, hb = qq >> 1, sg = (qq & 1) * 8;
                const unsigned* sbp = W + (bn + rb) * Ku + it * 32 + hb * 16 + sg;
                unsigned* dbp = Sb + hb * (64 * 16) + rb * 16 + sg;
                cp16(dbp, sbp); cp16(dbp + 4, sbp + 4);
            }
        } else {
            int row = tid >> 1, half = tid & 1;
            const unsigned* src = A + (bm + row) * Ku + it * 16 + half * 8;
            unsigned* dst = Sa + half * (128 * 8) + row * 8;
            cp16(dst, src); cp16(dst + 4, src + 4);
            const unsigned* sbp = W + (bn + row) * Ku + it * 16 + half * 8;
            unsigned* dbp = Sb + half * (128 * 8) + row * 8;
            cp16(dbp, sbp); cp16(dbp + 4, sbp + 4);
        }
    };

    const int nIter = K >> 5;
    issue(0, 0); CPA_COMMIT;
    issue(1, 1); CPA_COMMIT;

    for (int it = 0; it < nIter; it++) {
        CPA_WAIT1;
        __syncthreads();
        if (it + 2 < nIter) issue((it + 2) % 3, it + 2);
        CPA_COMMIT;

        const unsigned* Sa = sm + (it % 3) * (ASZ + BSZ);
        const unsigned* Sb = Sa + ASZ;
        #pragma unroll
        for (int sc = 0; sc < 2; sc++) {
            const unsigned* Asc = Sa + sc * (128 * RS);
            const unsigned* Bsc = Sb + sc * (NT * RS);
            if (SPLIT) {
                unsigned bhi[NI][2], blo[NI][2];
                #pragma unroll
                for (int ni = 0; ni < NI; ni++) {
                    uint4 f = *reinterpret_cast<const uint4*>(
                        Bsc + (wn * (NT/4) + ni * 8 + gr) * 16 + tc * 4);
                    bhi[ni][0] = f.x; blo[ni][0] = f.y;
                    bhi[ni][1] = f.z; blo[ni][1] = f.w;
                }
                unsigned ahi[4][4], alo[4][4];
                #pragma unroll
                for (int mi = 0; mi < 4; mi++) {
                    int r = wm * 64 + mi * 16 + gr;
                    uint4 f0 = *reinterpret_cast<const uint4*>(Asc + r * 16 + tc * 4);
                    uint4 f1 = *reinterpret_cast<const uint4*>(Asc + (r + 8) * 16 + tc * 4);
                    ahi[mi][0] = f0.x; ahi[mi][1] = f1.x; ahi[mi][2] = f0.z; ahi[mi][3] = f1.z;
                    alo[mi][0] = f0.y; alo[mi][1] = f1.y; alo[mi][2] = f0.w; alo[mi][3] = f1.w;
                }
                // pass 1: hi*hi (all independent)
                #pragma unroll
                for (int mi = 0; mi < 4; mi++)
                    #pragma unroll
                    for (int ni = 0; ni < NI; ni++)
                        mma_f16(acc[mi][ni], ahi[mi], bhi[ni]);
                // pass 2: hi*lo
                #pragma unroll
                for (int mi = 0; mi < 4; mi++)
                    #pragma unroll
                    for (int ni = 0; ni < NI; ni++)
                        mma_f16(acc[mi][ni], ahi[mi], blo[ni]);
                // pass 3: lo*hi
                #pragma unroll
                for (int mi = 0; mi < 4; mi++)
                    #pragma unroll
                    for (int ni = 0; ni < NI; ni++)
                        mma_f16(acc[mi][ni], alo[mi], bhi[ni]);
            } else {
                unsigned bf[NI][2];
                #pragma unroll
                for (int ni = 0; ni < NI; ni++) {
                    uint2 f = *reinterpret_cast<const uint2*>(
                        Bsc + (wn * (NT/4) + ni * 8 + gr) * 8 + tc * 2);
                    bf[ni][0] = f.x; bf[ni][1] = f.y;
                }
                unsigned af[4][4];
                #pragma unroll
                for (int mi = 0; mi < 4; mi++) {
                    int r = wm * 64 + mi * 16 + gr;
                    uint2 f0 = *reinterpret_cast<const uint2*>(Asc + r * 8 + tc * 2);
                    uint2 f1 = *reinterpret_cast<const uint2*>(Asc + (r + 8) * 8 + tc * 2);
                    af[mi][0] = f0.x; af[mi][1] = f1.x; af[mi][2] = f0.y; af[mi][3] = f1.y;
                }
                #pragma unroll
                for (int mi = 0; mi < 4; mi++)
                    #pragma unroll
                    for (int ni = 0; ni < NI; ni++)
                        mma_f16(acc[mi][ni], af[mi], bf[ni]);
            }
        }
    }

    // epilogue
    #pragma unroll
    for (int mi = 0; mi < 4; mi++) {
        #pragma unroll
        for (int ni = 0; ni < NI; ni++) {
            long row = bm + wm * 64 + mi * 16 + gr;
            int col = (int)bn + wn * (NT/4) + ni * 8 + tc * 2;
            float* a = acc[mi][ni];
            long i0 = row * (long)N + col;
            long i1 = (row + 8) * (long)N + col;
            if (EPI == 3) {
                float2 e0 = *reinterpret_cast<const float2*>(&E[i0]);
                float2 e1 = *reinterpret_cast<const float2*>(&E[i1]);
                uint2 w0 = split2(silu_f(a[0]) * e0.x, silu_f(a[1]) * e0.y);
                uint2 w1 = split2(silu_f(a[2]) * e1.x, silu_f(a[3]) * e1.y);
                int kc = col >> 4, p = (col >> 1) & 7;
                int pos = spos(p);
                *reinterpret_cast<uint2*>(CP + row * (long)N + kc * 16 + pos)       = w0;
                *reinterpret_cast<uint2*>(CP + (row + 8) * (long)N + kc * 16 + pos) = w1;
            } else {
                float2 o0, o1;
                if (EPI == 0) {
                    o0 = make_float2(a[0], a[1]);
                    o1 = make_float2(a[2], a[3]);
                } else if (EPI == 1) {
                    float2 c0 = *reinterpret_cast<float2*>(&C[i0]);
                    float2 c1 = *reinterpret_cast<float2*>(&C[i1]);
                    o0 = make_float2(c0.x + a[0], c0.y + a[1]);
                    o1 = make_float2(c1.x + a[2], c1.y + a[3]);
                } else {
                    float2 c0 = *reinterpret_cast<float2*>(&C[i0]);
                    float2 c1 = *reinterpret_cast<float2*>(&C[i1]);
                    float2 e0 = *reinterpret_cast<const float2*>(&E[i0]);
                    float2 e1 = *reinterpret_cast<const float2*>(&E[i1]);
                    o0 = make_float2(c0.x + a[0]*e0.x, c0.y + a[1]*e0.y);
                    o1 = make_float2(c1.x + a[2]*e1.x, c1.y + a[3]*e1.y);
                }
                *reinterpret_cast<float2*>(&C[i0]) = o0;
                *reinterpret_cast<float2*>(&C[i1]) = o1;
            }
        }
    }
}

// ---------------- decay attention with band pruning; emits packed silu(out) ---------
__global__ void __launch_bounds__(256) decay_attn(
    const float* __restrict__ Q, const float* __restrict__ NLv,
    const float* __restrict__ NM, unsigned* __restrict__ AOp)
{
    const int it = blockIdx.x;
    const int dt = blockIdx.y;
    const int b  = blockIdx.z;
    const float* q  = Q + (long)b*SS*DIM + dt*64;
    const float* nl = NLv + (long)b*SS;
    const float* nlmax = NM + b*(SS/64);
    __shared__ float qs[64][64];
    __shared__ float nls[64];
    __shared__ float sgs[64];
    const int tid = threadIdx.x;
    const int tx = tid & 15, ty = tid >> 4;
    float acc[4][4] = {};
    const int i0 = it*64 + ty*4;

    for (int jt = 0; jt <= it; jt++) {
        if (jt < it) {
            float dmin = (float)(it*64 - (jt*64 + 63));
            if (nlmax[jt] * dmin < -40.0f) continue;
        }
        {
            int r = tid >> 4;
            int c = (tid & 15) * 4;
            #pragma unroll
            for (int rr = 0; rr < 64; rr += 16) {
                float4 v = *reinterpret_cast<const float4*>(
                    q + (long)(jt*64 + r + rr) * DIM + c);
                *reinterpret_cast<float4*>(&qs[r + rr][c]) = v;
            }
        }
        if (tid < 64) {
            float xv = nl[jt*64 + tid];
            nls[tid] = xv;
            sgs[tid] = expf(xv);
        }
        __syncthreads();

        if (jt < it) {
            #pragma unroll 2
            for (int j = 0; j < 64; j++) {
                float s = sgs[j];
                float w = expf(nls[j] * (float)(i0 - (jt*64 + j)));
                float4 qv = *reinterpret_cast<const float4*>(&qs[j][tx*4]);
                #pragma unroll
                for (int ii = 0; ii < 4; ii++) {
                    acc[ii][0] += w * qv.x;
                    acc[ii][1] += w * qv.y;
                    acc[ii][2] += w * qv.z;
                    acc[ii][3] += w * qv.w;
                    w *= s;
                }
            }
        } else {
            for (int j = 0; j < 64; j++) {
                int jg = jt*64 + j;
                float4 qv = *reinterpret_cast<const float4*>(&qs[j][tx*4]);
                #pragma unroll
                for (int ii = 0; ii < 4; ii++) {
                    int d = i0 + ii - jg;
                    float w = (d >= 0) ? expf(nls[j] * (float)d) : 0.0f;
                    acc[ii][0] += w * qv.x;
                    acc[ii][1] += w * qv.y;
                    acc[ii][2] += w * qv.z;
                    acc[ii][3] += w * qv.w;
                }
            }
        }
        __syncthreads();
    }

    const int kc = dt * 4 + (tx >> 2);
    const int p0 = 2 * (tx & 3);
    const int pos0 = spos(p0), pos1 = spos(p0 + 1);
    #pragma unroll
    for (int ii = 0; ii < 4; ii++) {
        long r = (long)b * SS + i0 + ii;
        uint2 w0 = split2(silu_f(acc[ii][0]), silu_f(acc[ii][1]));
        uint2 w1 = split2(silu_f(acc[ii][2]), silu_f(acc[ii][3]));
        unsigned* base = AOp + r * DIM + kc * 16;
        *reinterpret_cast<uint2*>(base + pos0) = w0;
        *reinterpret_cast<uint2*>(base + pos1) = w1;
    }
}

// ---------------- orchestration ----------------
extern "C" void kernel_launch(void* const* d_in, const int* in_sizes, int n_in,
                              void* d_out, int out_size) {
    const int*   tokens       = (const int*)  d_in[0];
    const float* emb          = (const float*)d_in[1];
    const float* decay_norm_w = (const float*)d_in[2];
    const float* lambda_w     = (const float*)d_in[3];
    const float* quantity_w   = (const float*)d_in[4];
    const float* gate_w       = (const float*)d_in[5];
    const float* output_w     = (const float*)d_in[6];
    const float* ffn_norm_w   = (const float*)d_in[7];
    const float* w_h          = (const float*)d_in[8];
    const float* w_g          = (const float*)d_in[9];
    const float* w_o          = (const float*)d_in[10];
    const float* out_norm_w   = (const float*)d_in[11];
    float* out = (float*)d_out;

    float *x, *q, *g, *a, *nl, *nm;
    unsigned *h_p, *f_p, *ao_p, *t_p, *hf_p, *emb_p;
    unsigned *wq_p, *wg_p, *wout_p, *whh_p, *wgg_p, *wo_p;
    cudaGetSymbolAddress((void**)&x,  g_x);
    cudaGetSymbolAddress((void**)&q,  g_q);
    cudaGetSymbolAddress((void**)&g,  g_g);
    cudaGetSymbolAddress((void**)&a,  g_a);
    cudaGetSymbolAddress((void**)&nl, g_nl);
    cudaGetSymbolAddress((void**)&nm, g_nlmax);
    cudaGetSymbolAddress((void**)&h_p,  g_h_p);
    cudaGetSymbolAddress((void**)&f_p,  g_f_p);
    cudaGetSymbolAddress((void**)&ao_p, g_ao_p);
    cudaGetSymbolAddress((void**)&t_p,  g_t_p);
    cudaGetSymbolAddress((void**)&hf_p, g_hf_p);
    cudaGetSymbolAddress((void**)&emb_p,g_emb_p);
    cudaGetSymbolAddress((void**)&wq_p,  g_wq_p);
    cudaGetSymbolAddress((void**)&wg_p,  g_wg_p);
    cudaGetSymbolAddress((void**)&wout_p,g_wout_p);
    cudaGetSymbolAddress((void**)&whh_p, g_whh_p);
    cudaGetSymbolAddress((void**)&wgg_p, g_wgg_p);
    cudaGetSymbolAddress((void**)&wo_p,  g_wo_p);

    const int SM_S64  = 3 * (128*32 +  64*32) * 4;   // 73728
    const int SM_P128 = 3 * (128*16 + 128*16) * 4;   // 49152
    cudaFuncSetAttribute(gemm_tc<true,64,0>,  cudaFuncAttributeMaxDynamicSharedMemorySize, SM_S64);
    cudaFuncSetAttribute(gemm_tc<true,64,1>,  cudaFuncAttributeMaxDynamicSharedMemorySize, SM_S64);
    cudaFuncSetAttribute(gemm_tc<true,64,2>,  cudaFuncAttributeMaxDynamicSharedMemorySize, SM_S64);
    cudaFuncSetAttribute(gemm_tc<true,64,3>,  cudaFuncAttributeMaxDynamicSharedMemorySize, SM_S64);
    cudaFuncSetAttribute(gemm_tc<false,128,0>,cudaFuncAttributeMaxDynamicSharedMemorySize, SM_P128);

    // one-time weight conversions (per forward)
    {
        long t4;
        t4 = (long)NLAYERS*DIM*DIM/4;
        convert_split<<<(unsigned)((t4+255)/256), 256>>>(quantity_w, wq_p,  t4, DIM);
        convert_split<<<(unsigned)((t4+255)/256), 256>>>(gate_w,     wg_p,  t4, DIM);
        convert_split<<<(unsigned)((t4+255)/256), 256>>>(output_w,   wout_p,t4, DIM);
        t4 = (long)NLAYERS*HID*DIM/4;
        convert_split<<<(unsigned)((t4+255)/256), 256>>>(w_h, whh_p, t4, DIM);
        convert_split<<<(unsigned)((t4+255)/256), 256>>>(w_g, wgg_p, t4, DIM);
        convert_split<<<(unsigned)((t4+255)/256), 256>>>(w_o, wo_p,  t4, HID);
        t4 = (long)VOCAB*DIM/4;
        convert_plain<<<(unsigned)((t4+255)/256), 256>>>(emb, emb_p, t4, DIM);
    }

    embed_kernel<<<M_TOT * (DIM/4) / 256, 256>>>(tokens, emb, x);

    dim3 g512 (DIM/64,    M_TOT/128);   // (8,  32)  NT=64
    dim3 gHID (HID/64,    M_TOT/128);   // (32, 32)  NT=64
    dim3 gV   (VOCAB/128, M_TOT/128);   // (250,32)  NT=128 plain
    dim3 gattn(SS/64, DIM/64, BB);

    for (int l = 0; l < NLAYERS; l++) {
        rmsnorm_kernel<true,0><<<M_TOT, 128>>>(x, decay_norm_w + l*DIM,
                                               lambda_w + l*DIM, h_p, nl);
        nlmax_kernel<<<M_TOT/64, 32>>>(nl, nm);
        gemm_tc<true,64,0><<<g512, 256, SM_S64>>>(h_p, wq_p + (long)l*DIM*DIM, q,
                                                  nullptr, nullptr, M_TOT, DIM, DIM);
        gemm_tc<true,64,0><<<g512, 256, SM_S64>>>(h_p, wg_p + (long)l*DIM*DIM, g,
                                                  nullptr, nullptr, M_TOT, DIM, DIM);
        decay_attn<<<gattn, 256>>>(q, nl, nm, ao_p);
        gemm_tc<true,64,2><<<g512, 256, SM_S64>>>(ao_p, wout_p + (long)l*DIM*DIM, x,
                                                  g, nullptr, M_TOT, DIM, DIM);
        rmsnorm_kernel<false,0><<<M_TOT, 128>>>(x, ffn_norm_w + l*DIM,
                                                nullptr, f_p, nullptr);
        gemm_tc<true,64,0><<<gHID, 256, SM_S64>>>(f_p, whh_p + (long)l*HID*DIM, a,
                                                  nullptr, nullptr, M_TOT, HID, DIM);
        gemm_tc<true,64,3><<<gHID, 256, SM_S64>>>(f_p, wgg_p + (long)l*HID*DIM, nullptr,
                                                  a, t_p, M_TOT, HID, DIM);
        gemm_tc<true,64,1><<<g512, 256, SM_S64>>>(t_p, wo_p + (long)l*DIM*HID, x,
                                                  nullptr, nullptr, M_TOT, DIM, HID);
    }

    rmsnorm_kernel<false,1><<<M_TOT, 128>>>(x, out_norm_w, nullptr, hf_p, nullptr);
    gemm_tc<false,128,0><<<gV, 256, SM_P128>>>(hf_p, emb_p, out, nullptr, nullptr,
                                               M_TOT, VOCAB, DIM);
}

// round 7
// speedup vs baseline: 1.1482x; 1.1274x over previous
#include <cuda_runtime.h>
#include <cuda_fp16.h>
#include <math.h>

#define DIM 512
#define HID 2048
#define NLAYERS 4
#define VOCAB 32000
#define BB 2
#define SS 2048
#define M_TOT (BB*SS)   // 4096

// ---------------- scratch (device globals; no allocation allowed) ----------------
__device__ float g_x [M_TOT*DIM];
__device__ float g_q [M_TOT*DIM];
__device__ float g_g [M_TOT*DIM];
__device__ float g_a [M_TOT*HID];
__device__ float g_nl[M_TOT];
__device__ float g_nlmax[M_TOT/64];
// packed split-fp16 (1 u32 per element)
__device__ unsigned g_h_p [M_TOT*DIM];
__device__ unsigned g_f_p [M_TOT*DIM];
__device__ unsigned g_ao_p[M_TOT*DIM];
__device__ unsigned g_t_p [M_TOT*HID];
__device__ unsigned g_wq_p  [NLAYERS*DIM*DIM];
__device__ unsigned g_wg_p  [NLAYERS*DIM*DIM];
__device__ unsigned g_wout_p[NLAYERS*DIM*DIM];
// packed plain-fp16 (0.5 u32 per element)
__device__ unsigned g_whh_p [NLAYERS*HID*DIM/2];
__device__ unsigned g_wgg_p [NLAYERS*HID*DIM/2];
__device__ unsigned g_wo_p  [NLAYERS*DIM*HID/2];
__device__ unsigned g_hf_p [M_TOT*DIM/2];
__device__ unsigned g_emb_p[VOCAB*DIM/2];

__device__ __forceinline__ float silu_f(float v) {
    return v / (1.0f + __expf(-v));
}

__device__ __forceinline__ unsigned hpack(__half a, __half b) {
    __half2 t = __halves2half2(a, b);
    return *reinterpret_cast<unsigned*>(&t);
}

__device__ __forceinline__ uint2 split2(float x0, float x1) {
    __half h0 = __float2half_rn(x0), h1 = __float2half_rn(x1);
    unsigned H = hpack(h0, h1);
    unsigned L = hpack(__float2half_rn(x0 - __half2float(h0)),
                       __float2half_rn(x1 - __half2float(h1)));
    return make_uint2(H, L);
}

__device__ __forceinline__ void mma_f16(float* c, const unsigned* a, const unsigned* b) {
    asm volatile(
        "mma.sync.aligned.m16n8k16.row.col.f32.f16.f16.f32 "
        "{%0,%1,%2,%3}, {%4,%5,%6,%7}, {%8,%9}, {%0,%1,%2,%3};"
        : "+f"(c[0]), "+f"(c[1]), "+f"(c[2]), "+f"(c[3])
        : "r"(a[0]), "r"(a[1]), "r"(a[2]), "r"(a[3]), "r"(b[0]), "r"(b[1]));
}

__device__ __forceinline__ void cp16(unsigned* dst, const unsigned* src) {
    unsigned d = (unsigned)__cvta_generic_to_shared(dst);
    asm volatile("cp.async.cg.shared.global [%0], [%1], 16;" :: "r"(d), "l"(src) : "memory");
}
#define CPA_COMMIT asm volatile("cp.async.commit_group;" ::: "memory")
#define CPA_WAIT1  asm volatile("cp.async.wait_group 1;" ::: "memory")

// layout helpers: within a 16-k chunk, pair p (k=2p,2p+1)
__device__ __forceinline__ int spos(int p) { return (p & 3) * 4 + ((p >> 2) << 1); }
__device__ __forceinline__ int ppos(int p) { return (p & 3) * 2 + (p >> 2); }

// ---------------- weight conversion (fp32 -> packed) ----------------
__global__ void convert_split(const float* __restrict__ src, unsigned* __restrict__ dst,
                              long total4, int K) {
    long idx = (long)blockIdx.x * 256 + threadIdx.x;
    if (idx >= total4) return;
    int perRow = K >> 2;
    long row = idx / perRow;
    int rem = (int)(idx - row * perRow);
    int kc = rem >> 2, i4 = rem & 3;
    float4 v = reinterpret_cast<const float4*>(src)[idx];
    unsigned* base = dst + row * (long)K + kc * 16;
    int p0 = 2 * i4;
    *reinterpret_cast<uint2*>(base + spos(p0))     = split2(v.x, v.y);
    *reinterpret_cast<uint2*>(base + spos(p0 + 1)) = split2(v.z, v.w);
}

__global__ void convert_plain(const float* __restrict__ src, unsigned* __restrict__ dst,
                              long total4, int K) {
    long idx = (long)blockIdx.x * 256 + threadIdx.x;
    if (idx >= total4) return;
    int perRow = K >> 2;
    long row = idx / perRow;
    int rem = (int)(idx - row * perRow);
    int kc = rem >> 2, i4 = rem & 3;
    float4 v = reinterpret_cast<const float4*>(src)[idx];
    unsigned* base = dst + row * (long)(K >> 1) + kc * 8;
    int p0 = 2 * i4;
    base[ppos(p0)]     = hpack(__float2half_rn(v.x), __float2half_rn(v.y));
    base[ppos(p0 + 1)] = hpack(__float2half_rn(v.z), __float2half_rn(v.w));
}

// ---------------- embedding gather ----------------
__global__ void embed_kernel(const int* __restrict__ tok,
                             const float* __restrict__ emb,
                             float* __restrict__ X) {
    long idx = (long)blockIdx.x * 256 + threadIdx.x;
    int row = (int)(idx >> 7);
    int c   = (int)(idx & 127);
    int t   = tok[row];
    reinterpret_cast<float4*>(X)[idx] =
        reinterpret_cast<const float4*>(emb + (long)t * DIM)[c];
}

// ---------------- RMSNorm -> packed output ----------------
template<bool LAM, int PACK>
__global__ void rmsnorm_kernel(const float* __restrict__ X,
                               const float* __restrict__ w,
                               const float* __restrict__ lam,
                               unsigned* __restrict__ Hp,
                               float* __restrict__ NL) {
    __shared__ float sb[4];
    __shared__ float s_scale;
    const int row = blockIdx.x;
    const int t = threadIdx.x;
    float4 v = reinterpret_cast<const float4*>(X + (long)row * DIM)[t];
    float ss = v.x*v.x + v.y*v.y + v.z*v.z + v.w*v.w;
    #pragma unroll
    for (int o = 16; o > 0; o >>= 1) ss += __shfl_down_sync(0xffffffffu, ss, o);
    if ((t & 31) == 0) sb[t >> 5] = ss;
    __syncthreads();
    if (t == 0) {
        float tot = sb[0] + sb[1] + sb[2] + sb[3];
        s_scale = rsqrtf(tot / (float)DIM + 1e-6f);
    }
    __syncthreads();
    const float sc = s_scale;
    float4 wv = reinterpret_cast<const float4*>(w)[t];
    float4 h;
    h.x = v.x * sc * wv.x;
    h.y = v.y * sc * wv.y;
    h.z = v.z * sc * wv.z;
    h.w = v.w * sc * wv.w;
    const int kc = t >> 2, i4 = t & 3;
    const int p0 = 2 * i4;
    if (PACK == 0) {
        unsigned* base = Hp + (long)row * DIM + kc * 16;
        *reinterpret_cast<uint2*>(base + spos(p0))     = split2(h.x, h.y);
        *reinterpret_cast<uint2*>(base + spos(p0 + 1)) = split2(h.z, h.w);
    } else {
        unsigned* base = Hp + (long)row * (DIM / 2) + kc * 8;
        base[ppos(p0)]     = hpack(__float2half_rn(h.x), __float2half_rn(h.y));
        base[ppos(p0 + 1)] = hpack(__float2half_rn(h.z), __float2half_rn(h.w));
    }
    if (LAM) {
        float4 lv = reinterpret_cast<const float4*>(lam)[t];
        float d = h.x*lv.x + h.y*lv.y + h.z*lv.z + h.w*lv.w;
        #pragma unroll
        for (int o = 16; o > 0; o >>= 1) d += __shfl_down_sync(0xffffffffu, d, o);
        __syncthreads();
        if ((t & 31) == 0) sb[t >> 5] = d;
        __syncthreads();
        if (t == 0) {
            float dot = sb[0] + sb[1] + sb[2] + sb[3];
            float nl = (dot >= 0.0f) ? -log1pf(expf(-dot))
                                     : (dot - log1pf(expf(dot)));
            NL[row] = nl;
        }
    }
}

__global__ void nlmax_kernel(const float* __restrict__ NL, float* __restrict__ NM) {
    int base = blockIdx.x * 64;
    int lid = threadIdx.x;
    float v = fmaxf(NL[base + lid], NL[base + 32 + lid]);
    #pragma unroll
    for (int o = 16; o > 0; o >>= 1) v = fmaxf(v, __shfl_xor_sync(0xffffffffu, v, o));
    if (lid == 0) NM[blockIdx.x] = v;
}

// ---------------- tensor-core NT GEMM, cp.async 3-stage, packed inputs --------------
// ASP/BSP: operand is split (hi+lo, 2 mma contributions) or plain fp16.
// ASP=1,BSP=1: 3 mmas/k16 (hi*hi + hi*lo + lo*hi). ASP=1,BSP=0: 2 (ahi*b + alo*b).
// ASP=0,BSP=0: 1.  EPI: 0 C=acc | 1 C+=acc | 2 C+=acc*E | 3 CP=packsplit(silu(acc)*E)
template<int ASP, int BSP, int NT, int EPI>
__global__ void __launch_bounds__(256, 2) gemm_tc(
    const unsigned* __restrict__ A, const unsigned* __restrict__ W,
    float* __restrict__ C, const float* __restrict__ E,
    unsigned* __restrict__ CP, int M, int N, int K)
{
    constexpr int RSA = ASP ? 16 : 8;     // u32 per row per 16-k subchunk
    constexpr int RSB = BSP ? 16 : 8;
    constexpr int ASZ = 128 * 2 * RSA;
    constexpr int BSZ = NT * 2 * RSB;
    constexpr int NI  = NT / 32;
    extern __shared__ unsigned sm[];

    const int tid  = threadIdx.x;
    const int lane = tid & 31;
    const int gr   = lane >> 2;
    const int tc   = lane & 3;
    const int warp = tid >> 5;
    const int wm   = warp >> 2;
    const int wn   = warp & 3;
    const long bm = (long)blockIdx.y * 128;
    const long bn = (long)blockIdx.x * NT;
    const long KuA = ASP ? K : (K >> 1);
    const long KuB = BSP ? K : (K >> 1);

    float acc[4][NI][4] = {};

    auto issue = [&](int s, int it) {
        unsigned* Sa = sm + s * (ASZ + BSZ);
        unsigned* Sb = Sa + ASZ;
        // A plane
        if (ASP) {
            int row = tid >> 1, half = tid & 1;
            const unsigned* src = A + (bm + row) * KuA + it * 32 + half * 16;
            unsigned* dst = Sa + half * (128 * 16) + row * 16;
            cp16(dst, src); cp16(dst + 4, src + 4);
            cp16(dst + 8, src + 8); cp16(dst + 12, src + 12);
        } else {
            int row = tid >> 1, half = tid & 1;
            const unsigned* src = A + (bm + row) * KuA + it * 16 + half * 8;
            unsigned* dst = Sa + half * (128 * 8) + row * 8;
            cp16(dst, src); cp16(dst + 4, src + 4);
        }
        // B plane
        if (BSP) {
            if (NT == 128) {
                int row = tid >> 1, half = tid & 1;
                const unsigned* sbp = W + (bn + row) * KuB + it * 32 + half * 16;
                unsigned* dbp = Sb + half * (128 * 16) + row * 16;
                cp16(dbp, sbp); cp16(dbp + 4, sbp + 4);
                cp16(dbp + 8, sbp + 8); cp16(dbp + 12, sbp + 12);
            } else {
                int rb = tid >> 2, qq = tid & 3, hb = qq >> 1, sg = (qq & 1) * 8;
                const unsigned* sbp = W + (bn + rb) * KuB + it * 32 + hb * 16 + sg;
                unsigned* dbp = Sb + hb * (64 * 16) + rb * 16 + sg;
                cp16(dbp, sbp); cp16(dbp + 4, sbp + 4);
            }
        } else {
            if (NT == 128) {
                int row = tid >> 1, half = tid & 1;
                const unsigned* sbp = W + (bn + row) * KuB + it * 16 + half * 8;
                unsigned* dbp = Sb + half * (128 * 8) + row * 8;
                cp16(dbp, sbp); cp16(dbp + 4, sbp + 4);
            } else {
                int rb = tid >> 2, qq = tid & 3, hb = qq >> 1, sg = (qq & 1) * 4;
                const unsigned* sbp = W + (bn + rb) * KuB + it * 16 + hb * 8 + sg;
                unsigned* dbp = Sb + hb * (64 * 8) + rb * 8 + sg;
                cp16(dbp, sbp);
            }
        }
    };

    const int nIter = K >> 5;
    issue(0, 0); CPA_COMMIT;
    issue(1, 1); CPA_COMMIT;

    for (int it = 0; it < nIter; it++) {
        CPA_WAIT1;
        __syncthreads();
        if (it + 2 < nIter) issue((it + 2) % 3, it + 2);
        CPA_COMMIT;

        const unsigned* Sa = sm + (it % 3) * (ASZ + BSZ);
        const unsigned* Sb = Sa + ASZ;
        #pragma unroll
        for (int sc = 0; sc < 2; sc++) {
            const unsigned* Asc = Sa + sc * (128 * RSA);
            const unsigned* Bsc = Sb + sc * (NT * RSB);

            // B fragments
            unsigned bhi[NI][2], blo[NI][2];
            #pragma unroll
            for (int ni = 0; ni < NI; ni++) {
                if (BSP) {
                    uint4 f = *reinterpret_cast<const uint4*>(
                        Bsc + (wn * (NT/4) + ni * 8 + gr) * 16 + tc * 4);
                    bhi[ni][0] = f.x; blo[ni][0] = f.y;
                    bhi[ni][1] = f.z; blo[ni][1] = f.w;
                } else {
                    uint2 f = *reinterpret_cast<const uint2*>(
                        Bsc + (wn * (NT/4) + ni * 8 + gr) * 8 + tc * 2);
                    bhi[ni][0] = f.x; bhi[ni][1] = f.y;
                }
            }
            // A fragments
            unsigned ahi[4][4], alo[4][4];
            #pragma unroll
            for (int mi = 0; mi < 4; mi++) {
                int r = wm * 64 + mi * 16 + gr;
                if (ASP) {
                    uint4 f0 = *reinterpret_cast<const uint4*>(Asc + r * 16 + tc * 4);
                    uint4 f1 = *reinterpret_cast<const uint4*>(Asc + (r + 8) * 16 + tc * 4);
                    ahi[mi][0] = f0.x; ahi[mi][1] = f1.x; ahi[mi][2] = f0.z; ahi[mi][3] = f1.z;
                    alo[mi][0] = f0.y; alo[mi][1] = f1.y; alo[mi][2] = f0.w; alo[mi][3] = f1.w;
                } else {
                    uint2 f0 = *reinterpret_cast<const uint2*>(Asc + r * 8 + tc * 2);
                    uint2 f1 = *reinterpret_cast<const uint2*>(Asc + (r + 8) * 8 + tc * 2);
                    ahi[mi][0] = f0.x; ahi[mi][1] = f1.x; ahi[mi][2] = f0.y; ahi[mi][3] = f1.y;
                }
            }

            // pass 1: hi*hi
            #pragma unroll
            for (int mi = 0; mi < 4; mi++)
                #pragma unroll
                for (int ni = 0; ni < NI; ni++)
                    mma_f16(acc[mi][ni], ahi[mi], bhi[ni]);
            // pass 2: lo(A)*hi(B)
            if (ASP) {
                #pragma unroll
                for (int mi = 0; mi < 4; mi++)
                    #pragma unroll
                    for (int ni = 0; ni < NI; ni++)
                        mma_f16(acc[mi][ni], alo[mi], bhi[ni]);
            }
            // pass 3: hi(A)*lo(B)
            if (BSP) {
                #pragma unroll
                for (int mi = 0; mi < 4; mi++)
                    #pragma unroll
                    for (int ni = 0; ni < NI; ni++)
                        mma_f16(acc[mi][ni], ahi[mi], blo[ni]);
            }
        }
    }

    // epilogue
    #pragma unroll
    for (int mi = 0; mi < 4; mi++) {
        #pragma unroll
        for (int ni = 0; ni < NI; ni++) {
            long row = bm + wm * 64 + mi * 16 + gr;
            int col = (int)bn + wn * (NT/4) + ni * 8 + tc * 2;
            float* a = acc[mi][ni];
            long i0 = row * (long)N + col;
            long i1 = (row + 8) * (long)N + col;
            if (EPI == 3) {
                float2 e0 = *reinterpret_cast<const float2*>(&E[i0]);
                float2 e1 = *reinterpret_cast<const float2*>(&E[i1]);
                uint2 w0 = split2(silu_f(a[0]) * e0.x, silu_f(a[1]) * e0.y);
                uint2 w1 = split2(silu_f(a[2]) * e1.x, silu_f(a[3]) * e1.y);
                int kc = col >> 4, p = (col >> 1) & 7;
                int pos = spos(p);
                *reinterpret_cast<uint2*>(CP + row * (long)N + kc * 16 + pos)       = w0;
                *reinterpret_cast<uint2*>(CP + (row + 8) * (long)N + kc * 16 + pos) = w1;
            } else {
                float2 o0, o1;
                if (EPI == 0) {
                    o0 = make_float2(a[0], a[1]);
                    o1 = make_float2(a[2], a[3]);
                } else if (EPI == 1) {
                    float2 c0 = *reinterpret_cast<float2*>(&C[i0]);
                    float2 c1 = *reinterpret_cast<float2*>(&C[i1]);
                    o0 = make_float2(c0.x + a[0], c0.y + a[1]);
                    o1 = make_float2(c1.x + a[2], c1.y + a[3]);
                } else {
                    float2 c0 = *reinterpret_cast<float2*>(&C[i0]);
                    float2 c1 = *reinterpret_cast<float2*>(&C[i1]);
                    float2 e0 = *reinterpret_cast<const float2*>(&E[i0]);
                    float2 e1 = *reinterpret_cast<const float2*>(&E[i1]);
                    o0 = make_float2(c0.x + a[0]*e0.x, c0.y + a[1]*e0.y);
                    o1 = make_float2(c1.x + a[2]*e1.x, c1.y + a[3]*e1.y);
                }
                *reinterpret_cast<float2*>(&C[i0]) = o0;
                *reinterpret_cast<float2*>(&C[i1]) = o1;
            }
        }
    }
}

// ---------------- decay attention with band pruning; emits packed silu(out) ---------
__global__ void __launch_bounds__(256) decay_attn(
    const float* __restrict__ Q, const float* __restrict__ NLv,
    const float* __restrict__ NM, unsigned* __restrict__ AOp)
{
    const int it = blockIdx.x;
    const int dt = blockIdx.y;
    const int b  = blockIdx.z;
    const float* q  = Q + (long)b*SS*DIM + dt*64;
    const float* nl = NLv + (long)b*SS;
    const float* nlmax = NM + b*(SS/64);
    __shared__ float qs[64][64];
    __shared__ float nls[64];
    __shared__ float sgs[64];
    const int tid = threadIdx.x;
    const int tx = tid & 15, ty = tid >> 4;
    float acc[4][4] = {};
    const int i0 = it*64 + ty*4;

    for (int jt = 0; jt <= it; jt++) {
        if (jt < it) {
            float dmin = (float)(it*64 - (jt*64 + 63));
            if (nlmax[jt] * dmin < -40.0f) continue;
        }
        {
            int r = tid >> 4;
            int c = (tid & 15) * 4;
            #pragma unroll
            for (int rr = 0; rr < 64; rr += 16) {
                float4 v = *reinterpret_cast<const float4*>(
                    q + (long)(jt*64 + r + rr) * DIM + c);
                *reinterpret_cast<float4*>(&qs[r + rr][c]) = v;
            }
        }
        if (tid < 64) {
            float xv = nl[jt*64 + tid];
            nls[tid] = xv;
            sgs[tid] = expf(xv);
        }
        __syncthreads();

        if (jt < it) {
            #pragma unroll 2
            for (int j = 0; j < 64; j++) {
                float s = sgs[j];
                float w = expf(nls[j] * (float)(i0 - (jt*64 + j)));
                float4 qv = *reinterpret_cast<const float4*>(&qs[j][tx*4]);
                #pragma unroll
                for (int ii = 0; ii < 4; ii++) {
                    acc[ii][0] += w * qv.x;
                    acc[ii][1] += w * qv.y;
                    acc[ii][2] += w * qv.z;
                    acc[ii][3] += w * qv.w;
                    w *= s;
                }
            }
        } else {
            for (int j = 0; j < 64; j++) {
                int jg = jt*64 + j;
                float4 qv = *reinterpret_cast<const float4*>(&qs[j][tx*4]);
                #pragma unroll
                for (int ii = 0; ii < 4; ii++) {
                    int d = i0 + ii - jg;
                    float w = (d >= 0) ? expf(nls[j] * (float)d) : 0.0f;
                    acc[ii][0] += w * qv.x;
                    acc[ii][1] += w * qv.y;
                    acc[ii][2] += w * qv.z;
                    acc[ii][3] += w * qv.w;
                }
            }
        }
        __syncthreads();
    }

    const int kc = dt * 4 + (tx >> 2);
    const int p0 = 2 * (tx & 3);
    const int pos0 = spos(p0), pos1 = spos(p0 + 1);
    #pragma unroll
    for (int ii = 0; ii < 4; ii++) {
        long r = (long)b * SS + i0 + ii;
        uint2 w0 = split2(silu_f(acc[ii][0]), silu_f(acc[ii][1]));
        uint2 w1 = split2(silu_f(acc[ii][2]), silu_f(acc[ii][3]));
        unsigned* base = AOp + r * DIM + kc * 16;
        *reinterpret_cast<uint2*>(base + pos0) = w0;
        *reinterpret_cast<uint2*>(base + pos1) = w1;
    }
}

// ---------------- orchestration ----------------
extern "C" void kernel_launch(void* const* d_in, const int* in_sizes, int n_in,
                              void* d_out, int out_size) {
    const int*   tokens       = (const int*)  d_in[0];
    const float* emb          = (const float*)d_in[1];
    const float* decay_norm_w = (const float*)d_in[2];
    const float* lambda_w     = (const float*)d_in[3];
    const float* quantity_w   = (const float*)d_in[4];
    const float* gate_w       = (const float*)d_in[5];
    const float* output_w     = (const float*)d_in[6];
    const float* ffn_norm_w   = (const float*)d_in[7];
    const float* w_h          = (const float*)d_in[8];
    const float* w_g          = (const float*)d_in[9];
    const float* w_o          = (const float*)d_in[10];
    const float* out_norm_w   = (const float*)d_in[11];
    float* out = (float*)d_out;

    float *x, *q, *g, *a, *nl, *nm;
    unsigned *h_p, *f_p, *ao_p, *t_p, *hf_p, *emb_p;
    unsigned *wq_p, *wg_p, *wout_p, *whh_p, *wgg_p, *wo_p;
    cudaGetSymbolAddress((void**)&x,  g_x);
    cudaGetSymbolAddress((void**)&q,  g_q);
    cudaGetSymbolAddress((void**)&g,  g_g);
    cudaGetSymbolAddress((void**)&a,  g_a);
    cudaGetSymbolAddress((void**)&nl, g_nl);
    cudaGetSymbolAddress((void**)&nm, g_nlmax);
    cudaGetSymbolAddress((void**)&h_p,  g_h_p);
    cudaGetSymbolAddress((void**)&f_p,  g_f_p);
    cudaGetSymbolAddress((void**)&ao_p, g_ao_p);
    cudaGetSymbolAddress((void**)&t_p,  g_t_p);
    cudaGetSymbolAddress((void**)&hf_p, g_hf_p);
    cudaGetSymbolAddress((void**)&emb_p,g_emb_p);
    cudaGetSymbolAddress((void**)&wq_p,  g_wq_p);
    cudaGetSymbolAddress((void**)&wg_p,  g_wg_p);
    cudaGetSymbolAddress((void**)&wout_p,g_wout_p);
    cudaGetSymbolAddress((void**)&whh_p, g_whh_p);
    cudaGetSymbolAddress((void**)&wgg_p, g_wgg_p);
    cudaGetSymbolAddress((void**)&wo_p,  g_wo_p);

    const int SM_11_64  = 3 * (128*32 + 64*32) * 4;   // 73728
    const int SM_10_64  = 3 * (128*32 + 64*16) * 4;   // 61440
    const int SM_00_128 = 3 * (128*16 + 128*16) * 4;  // 49152
    cudaFuncSetAttribute(gemm_tc<1,1,64,0>,  cudaFuncAttributeMaxDynamicSharedMemorySize, SM_11_64);
    cudaFuncSetAttribute(gemm_tc<1,1,64,2>,  cudaFuncAttributeMaxDynamicSharedMemorySize, SM_11_64);
    cudaFuncSetAttribute(gemm_tc<1,0,64,0>,  cudaFuncAttributeMaxDynamicSharedMemorySize, SM_10_64);
    cudaFuncSetAttribute(gemm_tc<1,0,64,1>,  cudaFuncAttributeMaxDynamicSharedMemorySize, SM_10_64);
    cudaFuncSetAttribute(gemm_tc<1,0,64,3>,  cudaFuncAttributeMaxDynamicSharedMemorySize, SM_10_64);
    cudaFuncSetAttribute(gemm_tc<0,0,128,0>, cudaFuncAttributeMaxDynamicSharedMemorySize, SM_00_128);

    // one-time weight conversions (per forward)
    {
        long t4;
        t4 = (long)NLAYERS*DIM*DIM/4;
        convert_split<<<(unsigned)((t4+255)/256), 256>>>(quantity_w, wq_p,  t4, DIM);
        convert_split<<<(unsigned)((t4+255)/256), 256>>>(gate_w,     wg_p,  t4, DIM);
        convert_split<<<(unsigned)((t4+255)/256), 256>>>(output_w,   wout_p,t4, DIM);
        t4 = (long)NLAYERS*HID*DIM/4;
        convert_plain<<<(unsigned)((t4+255)/256), 256>>>(w_h, whh_p, t4, DIM);
        convert_plain<<<(unsigned)((t4+255)/256), 256>>>(w_g, wgg_p, t4, DIM);
        convert_plain<<<(unsigned)((t4+255)/256), 256>>>(w_o, wo_p,  t4, HID);
        t4 = (long)VOCAB*DIM/4;
        convert_plain<<<(unsigned)((t4+255)/256), 256>>>(emb, emb_p, t4, DIM);
    }

    embed_kernel<<<M_TOT * (DIM/4) / 256, 256>>>(tokens, emb, x);

    dim3 g512 (DIM/64,    M_TOT/128);   // (8,  32)  NT=64
    dim3 gHID (HID/64,    M_TOT/128);   // (32, 32)  NT=64
    dim3 gV   (VOCAB/128, M_TOT/128);   // (250,32)  NT=128
    dim3 gattn(SS/64, DIM/64, BB);

    for (int l = 0; l < NLAYERS; l++) {
        rmsnorm_kernel<true,0><<<M_TOT, 128>>>(x, decay_norm_w + l*DIM,
                                               lambda_w + l*DIM, h_p, nl);
        nlmax_kernel<<<M_TOT/64, 32>>>(nl, nm);
        gemm_tc<1,1,64,0><<<g512, 256, SM_11_64>>>(h_p, wq_p + (long)l*DIM*DIM, q,
                                                   nullptr, nullptr, M_TOT, DIM, DIM);
        gemm_tc<1,1,64,0><<<g512, 256, SM_11_64>>>(h_p, wg_p + (long)l*DIM*DIM, g,
                                                   nullptr, nullptr, M_TOT, DIM, DIM);
        decay_attn<<<gattn, 256>>>(q, nl, nm, ao_p);
        gemm_tc<1,1,64,2><<<g512, 256, SM_11_64>>>(ao_p, wout_p + (long)l*DIM*DIM, x,
                                                   g, nullptr, M_TOT, DIM, DIM);
        rmsnorm_kernel<false,0><<<M_TOT, 128>>>(x, ffn_norm_w + l*DIM,
                                                nullptr, f_p, nullptr);
        gemm_tc<1,0,64,0><<<gHID, 256, SM_10_64>>>(f_p, whh_p + (long)l*HID*DIM/2, a,
                                                   nullptr, nullptr, M_TOT, HID, DIM);
        gemm_tc<1,0,64,3><<<gHID, 256, SM_10_64>>>(f_p, wgg_p + (long)l*HID*DIM/2, nullptr,
                                                   a, t_p, M_TOT, HID, DIM);
        gemm_tc<1,0,64,1><<<g512, 256, SM_10_64>>>(t_p, wo_p + (long)l*DIM*HID/2, x,
                                                   nullptr, nullptr, M_TOT, DIM, HID);
    }

    rmsnorm_kernel<false,1><<<M_TOT, 128>>>(x, out_norm_w, nullptr, hf_p, nullptr);
    gemm_tc<0,0,128,0><<<gV, 256, SM_00_128>>>(hf_p, emb_p, out, nullptr, nullptr,
                                               M_TOT, VOCAB, DIM);
}

// round 8
// speedup vs baseline: 1.1798x; 1.0276x over previous
#include <cuda_runtime.h>
#include <cuda_fp16.h>
#include <math.h>

#define DIM 512
#define HID 2048
#define NLAYERS 4
#define VOCAB 32000
#define BB 2
#define SS 2048
#define M_TOT (BB*SS)   // 4096

// ---------------- scratch (device globals; no allocation allowed) ----------------
__device__ float g_x [M_TOT*DIM];
__device__ float g_q [M_TOT*DIM];
__device__ float g_g [M_TOT*DIM];
__device__ float g_a [M_TOT*HID];
__device__ float g_nl[M_TOT];
__device__ float g_nlmax[M_TOT/64];
// packed split-fp16 (1 u32 per element)
__device__ unsigned g_h_p [M_TOT*DIM];
__device__ unsigned g_f_p [M_TOT*DIM];
__device__ unsigned g_ao_p[M_TOT*DIM];
__device__ unsigned g_t_p [M_TOT*HID];
__device__ unsigned g_wq_p  [NLAYERS*DIM*DIM];
__device__ unsigned g_wg_p  [NLAYERS*DIM*DIM];
__device__ unsigned g_wout_p[NLAYERS*DIM*DIM];
// packed plain-fp16 (0.5 u32 per element)
__device__ unsigned g_whh_p [NLAYERS*HID*DIM/2];
__device__ unsigned g_wgg_p [NLAYERS*HID*DIM/2];
__device__ unsigned g_wo_p  [NLAYERS*DIM*HID/2];
__device__ unsigned g_hf_p [M_TOT*DIM/2];
__device__ unsigned g_emb_p[VOCAB*DIM/2];

__device__ __forceinline__ float silu_f(float v) {
    return v / (1.0f + __expf(-v));
}

__device__ __forceinline__ unsigned hpack(__half a, __half b) {
    __half2 t = __halves2half2(a, b);
    return *reinterpret_cast<unsigned*>(&t);
}

__device__ __forceinline__ uint2 split2(float x0, float x1) {
    __half h0 = __float2half_rn(x0), h1 = __float2half_rn(x1);
    unsigned H = hpack(h0, h1);
    unsigned L = hpack(__float2half_rn(x0 - __half2float(h0)),
                       __float2half_rn(x1 - __half2float(h1)));
    return make_uint2(H, L);
}

__device__ __forceinline__ void mma_f16(float* c, const unsigned* a, const unsigned* b) {
    asm volatile(
        "mma.sync.aligned.m16n8k16.row.col.f32.f16.f16.f32 "
        "{%0,%1,%2,%3}, {%4,%5,%6,%7}, {%8,%9}, {%0,%1,%2,%3};"
        : "+f"(c[0]), "+f"(c[1]), "+f"(c[2]), "+f"(c[3])
        : "r"(a[0]), "r"(a[1]), "r"(a[2]), "r"(a[3]), "r"(b[0]), "r"(b[1]));
}

__device__ __forceinline__ void cp16(unsigned* dst, const unsigned* src) {
    unsigned d = (unsigned)__cvta_generic_to_shared(dst);
    asm volatile("cp.async.cg.shared.global [%0], [%1], 16;" :: "r"(d), "l"(src) : "memory");
}
#define CPA_COMMIT asm volatile("cp.async.commit_group;" ::: "memory")
#define CPA_WAIT1  asm volatile("cp.async.wait_group 1;" ::: "memory")

// layout helpers: within a 16-k chunk, pair p (k=2p,2p+1)
__device__ __forceinline__ int spos(int p) { return (p & 3) * 4 + ((p >> 2) << 1); }
__device__ __forceinline__ int ppos(int p) { return (p & 3) * 2 + (p >> 2); }

// ---------------- fused weight conversion (single launch) ----------------
__device__ __forceinline__ void conv_split_one(const float* __restrict__ src,
                                               unsigned* __restrict__ dst,
                                               long idx, int K) {
    int perRow = K >> 2;
    long row = idx / perRow;
    int rem = (int)(idx - row * perRow);
    int kc = rem >> 2, i4 = rem & 3;
    float4 v = reinterpret_cast<const float4*>(src)[idx];
    unsigned* base = dst + row * (long)K + kc * 16;
    int p0 = 2 * i4;
    *reinterpret_cast<uint2*>(base + spos(p0))     = split2(v.x, v.y);
    *reinterpret_cast<uint2*>(base + spos(p0 + 1)) = split2(v.z, v.w);
}
__device__ __forceinline__ void conv_plain_one(const float* __restrict__ src,
                                               unsigned* __restrict__ dst,
                                               long idx, int K) {
    int perRow = K >> 2;
    long row = idx / perRow;
    int rem = (int)(idx - row * perRow);
    int kc = rem >> 2, i4 = rem & 3;
    float4 v = reinterpret_cast<const float4*>(src)[idx];
    unsigned* base = dst + row * (long)(K >> 1) + kc * 8;
    int p0 = 2 * i4;
    base[ppos(p0)]     = hpack(__float2half_rn(v.x), __float2half_rn(v.y));
    base[ppos(p0 + 1)] = hpack(__float2half_rn(v.z), __float2half_rn(v.w));
}

#define CB_S (NLAYERS*DIM*DIM/4/256)   // 1024 blocks per DIMxDIM split matrix
#define CB_H (NLAYERS*HID*DIM/4/256)   // 4096 blocks per HIDxDIM plain matrix
#define CB_V ((long)VOCAB*DIM/4/256)   // 16000 blocks for emb
#define CB_TOTAL (3*CB_S + 3*CB_H + (int)CB_V)  // 31360

__global__ void convert_all(
    const float* __restrict__ wq_s,  unsigned* __restrict__ wq_d,
    const float* __restrict__ wg_s,  unsigned* __restrict__ wg_d,
    const float* __restrict__ wo_s,  unsigned* __restrict__ wo_d,
    const float* __restrict__ whh_s, unsigned* __restrict__ whh_d,
    const float* __restrict__ wgg_s, unsigned* __restrict__ wgg_d,
    const float* __restrict__ wop_s, unsigned* __restrict__ wop_d,
    const float* __restrict__ emb_s, unsigned* __restrict__ emb_d)
{
    int b = blockIdx.x;
    if (b < CB_S) {
        conv_split_one(wq_s, wq_d, (long)b * 256 + threadIdx.x, DIM);
    } else if (b < 2*CB_S) {
        conv_split_one(wg_s, wg_d, (long)(b - CB_S) * 256 + threadIdx.x, DIM);
    } else if (b < 3*CB_S) {
        conv_split_one(wo_s, wo_d, (long)(b - 2*CB_S) * 256 + threadIdx.x, DIM);
    } else if (b < 3*CB_S + CB_H) {
        conv_plain_one(whh_s, whh_d, (long)(b - 3*CB_S) * 256 + threadIdx.x, DIM);
    } else if (b < 3*CB_S + 2*CB_H) {
        conv_plain_one(wgg_s, wgg_d, (long)(b - 3*CB_S - CB_H) * 256 + threadIdx.x, DIM);
    } else if (b < 3*CB_S + 3*CB_H) {
        conv_plain_one(wop_s, wop_d, (long)(b - 3*CB_S - 2*CB_H) * 256 + threadIdx.x, HID);
    } else {
        conv_plain_one(emb_s, emb_d, (long)(b - 3*CB_S - 3*CB_H) * 256 + threadIdx.x, DIM);
    }
}

// ---------------- embedding gather ----------------
__global__ void embed_kernel(const int* __restrict__ tok,
                             const float* __restrict__ emb,
                             float* __restrict__ X) {
    long idx = (long)blockIdx.x * 256 + threadIdx.x;
    int row = (int)(idx >> 7);
    int c   = (int)(idx & 127);
    int t   = tok[row];
    reinterpret_cast<float4*>(X)[idx] =
        reinterpret_cast<const float4*>(emb + (long)t * DIM)[c];
}

// ---------------- RMSNorm -> packed output ----------------
template<bool LAM, int PACK>
__global__ void rmsnorm_kernel(const float* __restrict__ X,
                               const float* __restrict__ w,
                               const float* __restrict__ lam,
                               unsigned* __restrict__ Hp,
                               float* __restrict__ NL) {
    __shared__ float sb[4];
    __shared__ float s_scale;
    const int row = blockIdx.x;
    const int t = threadIdx.x;
    float4 v = reinterpret_cast<const float4*>(X + (long)row * DIM)[t];
    float ss = v.x*v.x + v.y*v.y + v.z*v.z + v.w*v.w;
    #pragma unroll
    for (int o = 16; o > 0; o >>= 1) ss += __shfl_down_sync(0xffffffffu, ss, o);
    if ((t & 31) == 0) sb[t >> 5] = ss;
    __syncthreads();
    if (t == 0) {
        float tot = sb[0] + sb[1] + sb[2] + sb[3];
        s_scale = rsqrtf(tot / (float)DIM + 1e-6f);
    }
    __syncthreads();
    const float sc = s_scale;
    float4 wv = reinterpret_cast<const float4*>(w)[t];
    float4 h;
    h.x = v.x * sc * wv.x;
    h.y = v.y * sc * wv.y;
    h.z = v.z * sc * wv.z;
    h.w = v.w * sc * wv.w;
    const int kc = t >> 2, i4 = t & 3;
    const int p0 = 2 * i4;
    if (PACK == 0) {
        unsigned* base = Hp + (long)row * DIM + kc * 16;
        *reinterpret_cast<uint2*>(base + spos(p0))     = split2(h.x, h.y);
        *reinterpret_cast<uint2*>(base + spos(p0 + 1)) = split2(h.z, h.w);
    } else {
        unsigned* base = Hp + (long)row * (DIM / 2) + kc * 8;
        base[ppos(p0)]     = hpack(__float2half_rn(h.x), __float2half_rn(h.y));
        base[ppos(p0 + 1)] = hpack(__float2half_rn(h.z), __float2half_rn(h.w));
    }
    if (LAM) {
        float4 lv = reinterpret_cast<const float4*>(lam)[t];
        float d = h.x*lv.x + h.y*lv.y + h.z*lv.z + h.w*lv.w;
        #pragma unroll
        for (int o = 16; o > 0; o >>= 1) d += __shfl_down_sync(0xffffffffu, d, o);
        __syncthreads();
        if ((t & 31) == 0) sb[t >> 5] = d;
        __syncthreads();
        if (t == 0) {
            float dot = sb[0] + sb[1] + sb[2] + sb[3];
            float nl = (dot >= 0.0f) ? -log1pf(expf(-dot))
                                     : (dot - log1pf(expf(dot)));
            NL[row] = nl;
        }
    }
}

__global__ void nlmax_kernel(const float* __restrict__ NL, float* __restrict__ NM) {
    int base = blockIdx.x * 64;
    int lid = threadIdx.x;
    float v = fmaxf(NL[base + lid], NL[base + 32 + lid]);
    #pragma unroll
    for (int o = 16; o > 0; o >>= 1) v = fmaxf(v, __shfl_xor_sync(0xffffffffu, v, o));
    if (lid == 0) NM[blockIdx.x] = v;
}

// ---------------- tensor-core NT GEMM, cp.async 3-stage, packed inputs --------------
// ASP/BSP: operand split (hi+lo) vs plain fp16. mmas/k16: 3 (1,1) / 2 (1,0) / 1 (0,0).
// EPI: 0 C=acc | 1 C+=acc | 2 C+=acc*E | 3 CP=packsplit(silu(acc)*E)
template<int ASP, int BSP, int NT, int EPI>
__global__ void __launch_bounds__(256, 2) gemm_tc(
    const unsigned* __restrict__ A, const unsigned* __restrict__ W,
    float* __restrict__ C, const float* __restrict__ E,
    unsigned* __restrict__ CP, int M, int N, int K)
{
    constexpr int RSA = ASP ? 16 : 8;
    constexpr int RSB = BSP ? 16 : 8;
    constexpr int ASZ = 128 * 2 * RSA;
    constexpr int BSZ = NT * 2 * RSB;
    constexpr int NI  = NT / 32;
    extern __shared__ unsigned sm[];

    const int tid  = threadIdx.x;
    const int lane = tid & 31;
    const int gr   = lane >> 2;
    const int tc   = lane & 3;
    const int warp = tid >> 5;
    const int wm   = warp >> 2;
    const int wn   = warp & 3;
    const long bm = (long)blockIdx.y * 128;
    const long bn = (long)blockIdx.x * NT;
    const long KuA = ASP ? K : (K >> 1);
    const long KuB = BSP ? K : (K >> 1);

    float acc[4][NI][4] = {};

    auto issue = [&](int s, int it) {
        unsigned* Sa = sm + s * (ASZ + BSZ);
        unsigned* Sb = Sa + ASZ;
        if (ASP) {
            int row = tid >> 1, half = tid & 1;
            const unsigned* src = A + (bm + row) * KuA + it * 32 + half * 16;
            unsigned* dst = Sa + half * (128 * 16) + row * 16;
            cp16(dst, src); cp16(dst + 4, src + 4);
            cp16(dst + 8, src + 8); cp16(dst + 12, src + 12);
        } else {
            int row = tid >> 1, half = tid & 1;
            const unsigned* src = A + (bm + row) * KuA + it * 16 + half * 8;
            unsigned* dst = Sa + half * (128 * 8) + row * 8;
            cp16(dst, src); cp16(dst + 4, src + 4);
        }
        if (BSP) {
            if (NT == 128) {
                int row = tid >> 1, half = tid & 1;
                const unsigned* sbp = W + (bn + row) * KuB + it * 32 + half * 16;
                unsigned* dbp = Sb + half * (128 * 16) + row * 16;
                cp16(dbp, sbp); cp16(dbp + 4, sbp + 4);
                cp16(dbp + 8, sbp + 8); cp16(dbp + 12, sbp + 12);
            } else {
                int rb = tid >> 2, qq = tid & 3, hb = qq >> 1, sg = (qq & 1) * 8;
                const unsigned* sbp = W + (bn + rb) * KuB + it * 32 + hb * 16 + sg;
                unsigned* dbp = Sb + hb * (64 * 16) + rb * 16 + sg;
                cp16(dbp, sbp); cp16(dbp + 4, sbp + 4);
            }
        } else {
            if (NT == 128) {
                int row = tid >> 1, half = tid & 1;
                const unsigned* sbp = W + (bn + row) * KuB + it * 16 + half * 8;
                unsigned* dbp = Sb + half * (128 * 8) + row * 8;
                cp16(dbp, sbp); cp16(dbp + 4, sbp + 4);
            } else {
                int rb = tid >> 2, qq = tid & 3, hb = qq >> 1, sg = (qq & 1) * 4;
                const unsigned* sbp = W + (bn + rb) * KuB + it * 16 + hb * 8 + sg;
                unsigned* dbp = Sb + hb * (64 * 8) + rb * 8 + sg;
                cp16(dbp, sbp);
            }
        }
    };

    const int nIter = K >> 5;
    issue(0, 0); CPA_COMMIT;
    issue(1, 1); CPA_COMMIT;

    for (int it = 0; it < nIter; it++) {
        CPA_WAIT1;
        __syncthreads();
        if (it + 2 < nIter) issue((it + 2) % 3, it + 2);
        CPA_COMMIT;

        const unsigned* Sa = sm + (it % 3) * (ASZ + BSZ);
        const unsigned* Sb = Sa + ASZ;

        // prefetch B fragments for BOTH 16-k subchunks up front
        unsigned bhi[2][NI][2], blo[2][NI][2];
        #pragma unroll
        for (int sc = 0; sc < 2; sc++) {
            const unsigned* Bsc = Sb + sc * (NT * RSB);
            #pragma unroll
            for (int ni = 0; ni < NI; ni++) {
                if (BSP) {
                    uint4 f = *reinterpret_cast<const uint4*>(
                        Bsc + (wn * (NT/4) + ni * 8 + gr) * 16 + tc * 4);
                    bhi[sc][ni][0] = f.x; blo[sc][ni][0] = f.y;
                    bhi[sc][ni][1] = f.z; blo[sc][ni][1] = f.w;
                } else {
                    uint2 f = *reinterpret_cast<const uint2*>(
                        Bsc + (wn * (NT/4) + ni * 8 + gr) * 8 + tc * 2);
                    bhi[sc][ni][0] = f.x; bhi[sc][ni][1] = f.y;
                }
            }
        }

        #pragma unroll
        for (int sc = 0; sc < 2; sc++) {
            const unsigned* Asc = Sa + sc * (128 * RSA);
            unsigned ahi[4][4], alo[4][4];
            #pragma unroll
            for (int mi = 0; mi < 4; mi++) {
                int r = wm * 64 + mi * 16 + gr;
                if (ASP) {
                    uint4 f0 = *reinterpret_cast<const uint4*>(Asc + r * 16 + tc * 4);
                    uint4 f1 = *reinterpret_cast<const uint4*>(Asc + (r + 8) * 16 + tc * 4);
                    ahi[mi][0] = f0.x; ahi[mi][1] = f1.x; ahi[mi][2] = f0.z; ahi[mi][3] = f1.z;
                    alo[mi][0] = f0.y; alo[mi][1] = f1.y; alo[mi][2] = f0.w; alo[mi][3] = f1.w;
                } else {
                    uint2 f0 = *reinterpret_cast<const uint2*>(Asc + r * 8 + tc * 2);
                    uint2 f1 = *reinterpret_cast<const uint2*>(Asc + (r + 8) * 8 + tc * 2);
                    ahi[mi][0] = f0.x; ahi[mi][1] = f1.x; ahi[mi][2] = f0.y; ahi[mi][3] = f1.y;
                }
            }

            #pragma unroll
            for (int mi = 0; mi < 4; mi++)
                #pragma unroll
                for (int ni = 0; ni < NI; ni++)
                    mma_f16(acc[mi][ni], ahi[mi], bhi[sc][ni]);
            if (ASP) {
                #pragma unroll
                for (int mi = 0; mi < 4; mi++)
                    #pragma unroll
                    for (int ni = 0; ni < NI; ni++)
                        mma_f16(acc[mi][ni], alo[mi], bhi[sc][ni]);
            }
            if (BSP) {
                #pragma unroll
                for (int mi = 0; mi < 4; mi++)
                    #pragma unroll
                    for (int ni = 0; ni < NI; ni++)
                        mma_f16(acc[mi][ni], ahi[mi], blo[sc][ni]);
            }
        }
    }

    // epilogue
    #pragma unroll
    for (int mi = 0; mi < 4; mi++) {
        #pragma unroll
        for (int ni = 0; ni < NI; ni++) {
            long row = bm + wm * 64 + mi * 16 + gr;
            int col = (int)bn + wn * (NT/4) + ni * 8 + tc * 2;
            float* a = acc[mi][ni];
            long i0 = row * (long)N + col;
            long i1 = (row + 8) * (long)N + col;
            if (EPI == 3) {
                float2 e0 = *reinterpret_cast<const float2*>(&E[i0]);
                float2 e1 = *reinterpret_cast<const float2*>(&E[i1]);
                uint2 w0 = split2(silu_f(a[0]) * e0.x, silu_f(a[1]) * e0.y);
                uint2 w1 = split2(silu_f(a[2]) * e1.x, silu_f(a[3]) * e1.y);
                int kc = col >> 4, p = (col >> 1) & 7;
                int pos = spos(p);
                *reinterpret_cast<uint2*>(CP + row * (long)N + kc * 16 + pos)       = w0;
                *reinterpret_cast<uint2*>(CP + (row + 8) * (long)N + kc * 16 + pos) = w1;
            } else {
                float2 o0, o1;
                if (EPI == 0) {
                    o0 = make_float2(a[0], a[1]);
                    o1 = make_float2(a[2], a[3]);
                } else if (EPI == 1) {
                    float2 c0 = *reinterpret_cast<float2*>(&C[i0]);
                    float2 c1 = *reinterpret_cast<float2*>(&C[i1]);
                    o0 = make_float2(c0.x + a[0], c0.y + a[1]);
                    o1 = make_float2(c1.x + a[2], c1.y + a[3]);
                } else {
                    float2 c0 = *reinterpret_cast<float2*>(&C[i0]);
                    float2 c1 = *reinterpret_cast<float2*>(&C[i1]);
                    float2 e0 = *reinterpret_cast<const float2*>(&E[i0]);
                    float2 e1 = *reinterpret_cast<const float2*>(&E[i1]);
                    o0 = make_float2(c0.x + a[0]*e0.x, c0.y + a[1]*e0.y);
                    o1 = make_float2(c1.x + a[2]*e1.x, c1.y + a[3]*e1.y);
                }
                *reinterpret_cast<float2*>(&C[i0]) = o0;
                *reinterpret_cast<float2*>(&C[i1]) = o1;
            }
        }
    }
}

// ---------------- decay attention with band pruning; emits packed silu(out) ---------
__global__ void __launch_bounds__(256) decay_attn(
    const float* __restrict__ Q, const float* __restrict__ NLv,
    const float* __restrict__ NM, unsigned* __restrict__ AOp)
{
    const int it = blockIdx.x;
    const int dt = blockIdx.y;
    const int b  = blockIdx.z;
    const float* q  = Q + (long)b*SS*DIM + dt*64;
    const float* nl = NLv + (long)b*SS;
    const float* nlmax = NM + b*(SS/64);
    __shared__ float qs[64][64];
    __shared__ float nls[64];
    __shared__ float sgs[64];
    const int tid = threadIdx.x;
    const int tx = tid & 15, ty = tid >> 4;
    float acc[4][4] = {};
    const int i0 = it*64 + ty*4;

    for (int jt = 0; jt <= it; jt++) {
        if (jt < it) {
            // max weight in tile <= exp(nlmax * dmin); exp(-25)~1.4e-11 negligible
            float dmin = (float)(it*64 - (jt*64 + 63));
            if (nlmax[jt] * dmin < -25.0f) continue;
        }
        {
            int r = tid >> 4;
            int c = (tid & 15) * 4;
            #pragma unroll
            for (int rr = 0; rr < 64; rr += 16) {
                float4 v = *reinterpret_cast<const float4*>(
                    q + (long)(jt*64 + r + rr) * DIM + c);
                *reinterpret_cast<float4*>(&qs[r + rr][c]) = v;
            }
        }
        if (tid < 64) {
            float xv = nl[jt*64 + tid];
            nls[tid] = xv;
            sgs[tid] = expf(xv);
        }
        __syncthreads();

        if (jt < it) {
            #pragma unroll 2
            for (int j = 0; j < 64; j++) {
                float s = sgs[j];
                float w = expf(nls[j] * (float)(i0 - (jt*64 + j)));
                float4 qv = *reinterpret_cast<const float4*>(&qs[j][tx*4]);
                #pragma unroll
                for (int ii = 0; ii < 4; ii++) {
                    acc[ii][0] += w * qv.x;
                    acc[ii][1] += w * qv.y;
                    acc[ii][2] += w * qv.z;
                    acc[ii][3] += w * qv.w;
                    w *= s;
                }
            }
        } else {
            for (int j = 0; j < 64; j++) {
                int jg = jt*64 + j;
                float4 qv = *reinterpret_cast<const float4*>(&qs[j][tx*4]);
                #pragma unroll
                for (int ii = 0; ii < 4; ii++) {
                    int d = i0 + ii - jg;
                    float w = (d >= 0) ? expf(nls[j] * (float)d) : 0.0f;
                    acc[ii][0] += w * qv.x;
                    acc[ii][1] += w * qv.y;
                    acc[ii][2] += w * qv.z;
                    acc[ii][3] += w * qv.w;
                }
            }
        }
        __syncthreads();
    }

    const int kc = dt * 4 + (tx >> 2);
    const int p0 = 2 * (tx & 3);
    const int pos0 = spos(p0), pos1 = spos(p0 + 1);
    #pragma unroll
    for (int ii = 0; ii < 4; ii++) {
        long r = (long)b * SS + i0 + ii;
        uint2 w0 = split2(silu_f(acc[ii][0]), silu_f(acc[ii][1]));
        uint2 w1 = split2(silu_f(acc[ii][2]), silu_f(acc[ii][3]));
        unsigned* base = AOp + r * DIM + kc * 16;
        *reinterpret_cast<uint2*>(base + pos0) = w0;
        *reinterpret_cast<uint2*>(base + pos1) = w1;
    }
}

// ---------------- orchestration ----------------
extern "C" void kernel_launch(void* const* d_in, const int* in_sizes, int n_in,
                              void* d_out, int out_size) {
    const int*   tokens       = (const int*)  d_in[0];
    const float* emb          = (const float*)d_in[1];
    const float* decay_norm_w = (const float*)d_in[2];
    const float* lambda_w     = (const float*)d_in[3];
    const float* quantity_w   = (const float*)d_in[4];
    const float* gate_w       = (const float*)d_in[5];
    const float* output_w     = (const float*)d_in[6];
    const float* ffn_norm_w   = (const float*)d_in[7];
    const float* w_h          = (const float*)d_in[8];
    const float* w_g          = (const float*)d_in[9];
    const float* w_o          = (const float*)d_in[10];
    const float* out_norm_w   = (const float*)d_in[11];
    float* out = (float*)d_out;

    float *x, *q, *g, *a, *nl, *nm;
    unsigned *h_p, *f_p, *ao_p, *t_p, *hf_p, *emb_p;
    unsigned *wq_p, *wg_p, *wout_p, *whh_p, *wgg_p, *wo_p;
    cudaGetSymbolAddress((void**)&x,  g_x);
    cudaGetSymbolAddress((void**)&q,  g_q);
    cudaGetSymbolAddress((void**)&g,  g_g);
    cudaGetSymbolAddress((void**)&a,  g_a);
    cudaGetSymbolAddress((void**)&nl, g_nl);
    cudaGetSymbolAddress((void**)&nm, g_nlmax);
    cudaGetSymbolAddress((void**)&h_p,  g_h_p);
    cudaGetSymbolAddress((void**)&f_p,  g_f_p);
    cudaGetSymbolAddress((void**)&ao_p, g_ao_p);
    cudaGetSymbolAddress((void**)&t_p,  g_t_p);
    cudaGetSymbolAddress((void**)&hf_p, g_hf_p);
    cudaGetSymbolAddress((void**)&emb_p,g_emb_p);
    cudaGetSymbolAddress((void**)&wq_p,  g_wq_p);
    cudaGetSymbolAddress((void**)&wg_p,  g_wg_p);
    cudaGetSymbolAddress((void**)&wout_p,g_wout_p);
    cudaGetSymbolAddress((void**)&whh_p, g_whh_p);
    cudaGetSymbolAddress((void**)&wgg_p, g_wgg_p);
    cudaGetSymbolAddress((void**)&wo_p,  g_wo_p);

    const int SM_11_64  = 3 * (128*32 + 64*32) * 4;   // 73728
    const int SM_10_64  = 3 * (128*32 + 64*16) * 4;   // 61440
    const int SM_00_128 = 3 * (128*16 + 128*16) * 4;  // 49152
    cudaFuncSetAttribute(gemm_tc<1,1,64,0>,  cudaFuncAttributeMaxDynamicSharedMemorySize, SM_11_64);
    cudaFuncSetAttribute(gemm_tc<1,1,64,2>,  cudaFuncAttributeMaxDynamicSharedMemorySize, SM_11_64);
    cudaFuncSetAttribute(gemm_tc<1,0,64,0>,  cudaFuncAttributeMaxDynamicSharedMemorySize, SM_10_64);
    cudaFuncSetAttribute(gemm_tc<1,0,64,1>,  cudaFuncAttributeMaxDynamicSharedMemorySize, SM_10_64);
    cudaFuncSetAttribute(gemm_tc<1,0,64,3>,  cudaFuncAttributeMaxDynamicSharedMemorySize, SM_10_64);
    cudaFuncSetAttribute(gemm_tc<0,0,128,0>, cudaFuncAttributeMaxDynamicSharedMemorySize, SM_00_128);

    // one fused conversion launch (launch #0)
    convert_all<<<CB_TOTAL, 256>>>(
        quantity_w, wq_p, gate_w, wg_p, output_w, wout_p,
        w_h, whh_p, w_g, wgg_p, w_o, wo_p, emb, emb_p);

    embed_kernel<<<M_TOT * (DIM/4) / 256, 256>>>(tokens, emb, x);

    dim3 g512 (DIM/64,    M_TOT/128);   // (8,  32)  NT=64
    dim3 gHID (HID/64,    M_TOT/128);   // (32, 32)  NT=64
    dim3 gV   (VOCAB/128, M_TOT/128);   // (250,32)  NT=128
    dim3 gattn(SS/64, DIM/64, BB);

    for (int l = 0; l < NLAYERS; l++) {
        rmsnorm_kernel<true,0><<<M_TOT, 128>>>(x, decay_norm_w + l*DIM,
                                               lambda_w + l*DIM, h_p, nl);
        nlmax_kernel<<<M_TOT/64, 32>>>(nl, nm);
        gemm_tc<1,1,64,0><<<g512, 256, SM_11_64>>>(h_p, wq_p + (long)l*DIM*DIM, q,
                                                   nullptr, nullptr, M_TOT, DIM, DIM);
        gemm_tc<1,1,64,0><<<g512, 256, SM_11_64>>>(h_p, wg_p + (long)l*DIM*DIM, g,
                                                   nullptr, nullptr, M_TOT, DIM, DIM);
        decay_attn<<<gattn, 256>>>(q, nl, nm, ao_p);
        gemm_tc<1,1,64,2><<<g512, 256, SM_11_64>>>(ao_p, wout_p + (long)l*DIM*DIM, x,
                                                   g, nullptr, M_TOT, DIM, DIM);
        rmsnorm_kernel<false,0><<<M_TOT, 128>>>(x, ffn_norm_w + l*DIM,
                                                nullptr, f_p, nullptr);
        gemm_tc<1,0,64,0><<<gHID, 256, SM_10_64>>>(f_p, whh_p + (long)l*HID*DIM/2, a,
                                                   nullptr, nullptr, M_TOT, HID, DIM);
        gemm_tc<1,0,64,3><<<gHID, 256, SM_10_64>>>(f_p, wgg_p + (long)l*HID*DIM/2, nullptr,
                                                   a, t_p, M_TOT, HID, DIM);
        gemm_tc<1,0,64,1><<<g512, 256, SM_10_64>>>(t_p, wo_p + (long)l*DIM*HID/2, x,
                                                   nullptr, nullptr, M_TOT, DIM, HID);
    }

    rmsnorm_kernel<false,1><<<M_TOT, 128>>>(x, out_norm_w, nullptr, hf_p, nullptr);
    gemm_tc<0,0,128,0><<<gV, 256, SM_00_128>>>(hf_p, emb_p, out, nullptr, nullptr,
                                               M_TOT, VOCAB, DIM);
}

// round 9
// speedup vs baseline: 1.2847x; 1.0889x over previous
#include <cuda_runtime.h>
#include <cuda_fp16.h>
#include <math.h>

#define DIM 512
#define HID 2048
#define NLAYERS 4
#define VOCAB 32000
#define BB 2
#define SS 2048
#define M_TOT (BB*SS)   // 4096

// ---------------- scratch (device globals; no allocation allowed) ----------------
__device__ float g_x [M_TOT*DIM];
__device__ float g_qg[M_TOT*1024];       // [q | g] fused, row stride 1024
__device__ float g_a [M_TOT*HID];
__device__ float g_nl[M_TOT];
__device__ float g_nlmax[M_TOT/64];
// packed split-fp16 (1 u32 per element)
__device__ unsigned g_h_p [M_TOT*DIM];
__device__ unsigned g_f_p [M_TOT*DIM];
__device__ unsigned g_ao_p[M_TOT*DIM];
__device__ unsigned g_t_p [M_TOT*HID];
__device__ unsigned g_wqg_p [NLAYERS*1024*DIM];   // q rows then g rows per layer
__device__ unsigned g_wout_p[NLAYERS*DIM*DIM];
// packed plain-fp16 (0.5 u32 per element)
__device__ unsigned g_whh_p [NLAYERS*HID*DIM/2];
__device__ unsigned g_wgg_p [NLAYERS*HID*DIM/2];
__device__ unsigned g_wo_p  [NLAYERS*DIM*HID/2];
__device__ unsigned g_hf_p [M_TOT*DIM/2];
__device__ unsigned g_emb_p[VOCAB*DIM/2];

__device__ __forceinline__ float silu_f(float v) {
    return v / (1.0f + __expf(-v));
}

__device__ __forceinline__ unsigned hpack(__half a, __half b) {
    __half2 t = __halves2half2(a, b);
    return *reinterpret_cast<unsigned*>(&t);
}

__device__ __forceinline__ uint2 split2(float x0, float x1) {
    __half h0 = __float2half_rn(x0), h1 = __float2half_rn(x1);
    unsigned H = hpack(h0, h1);
    unsigned L = hpack(__float2half_rn(x0 - __half2float(h0)),
                       __float2half_rn(x1 - __half2float(h1)));
    return make_uint2(H, L);
}

__device__ __forceinline__ void mma_f16(float* c, const unsigned* a, const unsigned* b) {
    asm volatile(
        "mma.sync.aligned.m16n8k16.row.col.f32.f16.f16.f32 "
        "{%0,%1,%2,%3}, {%4,%5,%6,%7}, {%8,%9}, {%0,%1,%2,%3};"
        : "+f"(c[0]), "+f"(c[1]), "+f"(c[2]), "+f"(c[3])
        : "r"(a[0]), "r"(a[1]), "r"(a[2]), "r"(a[3]), "r"(b[0]), "r"(b[1]));
}

__device__ __forceinline__ void cp16(unsigned* dst, const unsigned* src) {
    unsigned d = (unsigned)__cvta_generic_to_shared(dst);
    asm volatile("cp.async.cg.shared.global [%0], [%1], 16;" :: "r"(d), "l"(src) : "memory");
}
#define CPA_COMMIT asm volatile("cp.async.commit_group;" ::: "memory")
#define CPA_WAIT1  asm volatile("cp.async.wait_group 1;" ::: "memory")

// layout helpers: within a 16-k chunk, pair p (k=2p,2p+1)
__device__ __forceinline__ int spos(int p) { return (p & 3) * 4 + ((p >> 2) << 1); }
__device__ __forceinline__ int ppos(int p) { return (p & 3) * 2 + (p >> 2); }

// ---------------- fused weight conversion (single launch) ----------------
// QGOFF >= 0: qg-fused layout, dst row = (srcrow/512)*1024 + QGOFF + srcrow%512
template<int QGOFF>
__device__ __forceinline__ void conv_split_one(const float* __restrict__ src,
                                               unsigned* __restrict__ dst,
                                               long idx, int K) {
    int perRow = K >> 2;
    long row = idx / perRow;
    int rem = (int)(idx - row * perRow);
    int kc = rem >> 2, i4 = rem & 3;
    float4 v = reinterpret_cast<const float4*>(src)[idx];
    long drow = (QGOFF >= 0) ? ((row >> 9) * 1024 + QGOFF + (row & 511)) : row;
    unsigned* base = dst + drow * (long)K + kc * 16;
    int p0 = 2 * i4;
    *reinterpret_cast<uint2*>(base + spos(p0))     = split2(v.x, v.y);
    *reinterpret_cast<uint2*>(base + spos(p0 + 1)) = split2(v.z, v.w);
}
__device__ __forceinline__ void conv_plain_one(const float* __restrict__ src,
                                               unsigned* __restrict__ dst,
                                               long idx, int K) {
    int perRow = K >> 2;
    long row = idx / perRow;
    int rem = (int)(idx - row * perRow);
    int kc = rem >> 2, i4 = rem & 3;
    float4 v = reinterpret_cast<const float4*>(src)[idx];
    unsigned* base = dst + row * (long)(K >> 1) + kc * 8;
    int p0 = 2 * i4;
    base[ppos(p0)]     = hpack(__float2half_rn(v.x), __float2half_rn(v.y));
    base[ppos(p0 + 1)] = hpack(__float2half_rn(v.z), __float2half_rn(v.w));
}

#define CB_S (NLAYERS*DIM*DIM/4/256)   // 1024 blocks per DIMxDIM split matrix
#define CB_H (NLAYERS*HID*DIM/4/256)   // 4096 blocks per HIDxDIM plain matrix
#define CB_V ((long)VOCAB*DIM/4/256)   // 16000 blocks for emb
#define CB_TOTAL (3*CB_S + 3*CB_H + (int)CB_V)  // 31360

__global__ void convert_all(
    const float* __restrict__ wq_s,  unsigned* __restrict__ wqg_d,
    const float* __restrict__ wg_s,
    const float* __restrict__ wo_s,  unsigned* __restrict__ wo_d,
    const float* __restrict__ whh_s, unsigned* __restrict__ whh_d,
    const float* __restrict__ wgg_s, unsigned* __restrict__ wgg_d,
    const float* __restrict__ wop_s, unsigned* __restrict__ wop_d,
    const float* __restrict__ emb_s, unsigned* __restrict__ emb_d)
{
    int b = blockIdx.x;
    if (b < CB_S) {
        conv_split_one<0>(wq_s, wqg_d, (long)b * 256 + threadIdx.x, DIM);
    } else if (b < 2*CB_S) {
        conv_split_one<512>(wg_s, wqg_d, (long)(b - CB_S) * 256 + threadIdx.x, DIM);
    } else if (b < 3*CB_S) {
        conv_split_one<-1>(wo_s, wo_d, (long)(b - 2*CB_S) * 256 + threadIdx.x, DIM);
    } else if (b < 3*CB_S + CB_H) {
        conv_plain_one(whh_s, whh_d, (long)(b - 3*CB_S) * 256 + threadIdx.x, DIM);
    } else if (b < 3*CB_S + 2*CB_H) {
        conv_plain_one(wgg_s, wgg_d, (long)(b - 3*CB_S - CB_H) * 256 + threadIdx.x, DIM);
    } else if (b < 3*CB_S + 3*CB_H) {
        conv_plain_one(wop_s, wop_d, (long)(b - 3*CB_S - 2*CB_H) * 256 + threadIdx.x, HID);
    } else {
        conv_plain_one(emb_s, emb_d, (long)(b - 3*CB_S - 3*CB_H) * 256 + threadIdx.x, DIM);
    }
}

// ---------------- embedding gather ----------------
__global__ void embed_kernel(const int* __restrict__ tok,
                             const float* __restrict__ emb,
                             float* __restrict__ X) {
    long idx = (long)blockIdx.x * 256 + threadIdx.x;
    int row = (int)(idx >> 7);
    int c   = (int)(idx & 127);
    int t   = tok[row];
    reinterpret_cast<float4*>(X)[idx] =
        reinterpret_cast<const float4*>(emb + (long)t * DIM)[c];
}

// ---------------- RMSNorm -> packed output ----------------
template<bool LAM, int PACK>
__global__ void rmsnorm_kernel(const float* __restrict__ X,
                               const float* __restrict__ w,
                               const float* __restrict__ lam,
                               unsigned* __restrict__ Hp,
                               float* __restrict__ NL) {
    __shared__ float sb[4];
    __shared__ float s_scale;
    const int row = blockIdx.x;
    const int t = threadIdx.x;
    float4 v = reinterpret_cast<const float4*>(X + (long)row * DIM)[t];
    float ss = v.x*v.x + v.y*v.y + v.z*v.z + v.w*v.w;
    #pragma unroll
    for (int o = 16; o > 0; o >>= 1) ss += __shfl_down_sync(0xffffffffu, ss, o);
    if ((t & 31) == 0) sb[t >> 5] = ss;
    __syncthreads();
    if (t == 0) {
        float tot = sb[0] + sb[1] + sb[2] + sb[3];
        s_scale = rsqrtf(tot / (float)DIM + 1e-6f);
    }
    __syncthreads();
    const float sc = s_scale;
    float4 wv = reinterpret_cast<const float4*>(w)[t];
    float4 h;
    h.x = v.x * sc * wv.x;
    h.y = v.y * sc * wv.y;
    h.z = v.z * sc * wv.z;
    h.w = v.w * sc * wv.w;
    const int kc = t >> 2, i4 = t & 3;
    const int p0 = 2 * i4;
    if (PACK == 0) {
        unsigned* base = Hp + (long)row * DIM + kc * 16;
        *reinterpret_cast<uint2*>(base + spos(p0))     = split2(h.x, h.y);
        *reinterpret_cast<uint2*>(base + spos(p0 + 1)) = split2(h.z, h.w);
    } else {
        unsigned* base = Hp + (long)row * (DIM / 2) + kc * 8;
        base[ppos(p0)]     = hpack(__float2half_rn(h.x), __float2half_rn(h.y));
        base[ppos(p0 + 1)] = hpack(__float2half_rn(h.z), __float2half_rn(h.w));
    }
    if (LAM) {
        float4 lv = reinterpret_cast<const float4*>(lam)[t];
        float d = h.x*lv.x + h.y*lv.y + h.z*lv.z + h.w*lv.w;
        #pragma unroll
        for (int o = 16; o > 0; o >>= 1) d += __shfl_down_sync(0xffffffffu, d, o);
        __syncthreads();
        if ((t & 31) == 0) sb[t >> 5] = d;
        __syncthreads();
        if (t == 0) {
            float dot = sb[0] + sb[1] + sb[2] + sb[3];
            float nl = (dot >= 0.0f) ? -log1pf(expf(-dot))
                                     : (dot - log1pf(expf(dot)));
            NL[row] = nl;
        }
    }
}

__global__ void nlmax_kernel(const float* __restrict__ NL, float* __restrict__ NM) {
    int base = blockIdx.x * 64;
    int lid = threadIdx.x;
    float v = fmaxf(NL[base + lid], NL[base + 32 + lid]);
    #pragma unroll
    for (int o = 16; o > 0; o >>= 1) v = fmaxf(v, __shfl_xor_sync(0xffffffffu, v, o));
    if (lid == 0) NM[blockIdx.x] = v;
}

// ---------------- tensor-core NT GEMM, cp.async 3-stage, NT=128 tiles ---------------
// ASP/BSP: operand split (hi+lo) vs plain fp16. mmas/k16: 3 (1,1) / 2 (1,0) / 1 (0,0).
// EPI: 0 C=acc | 1 C+=acc | 2 C+=acc*E | 3 CP=packsplit(silu(acc)*E).  ES: E row stride.
template<int ASP, int BSP, int EPI>
__global__ void __launch_bounds__(256) gemm_tc(
    const unsigned* __restrict__ A, const unsigned* __restrict__ W,
    float* __restrict__ C, const float* __restrict__ E,
    unsigned* __restrict__ CP, int M, int N, int K, int ES)
{
    constexpr int NT = 128;
    constexpr int RSA = ASP ? 16 : 8;
    constexpr int RSB = BSP ? 16 : 8;
    constexpr int ASZ = 128 * 2 * RSA;
    constexpr int BSZ = NT * 2 * RSB;
    constexpr int NI  = NT / 32;
    extern __shared__ unsigned sm[];

    const int tid  = threadIdx.x;
    const int lane = tid & 31;
    const int gr   = lane >> 2;
    const int tc   = lane & 3;
    const int warp = tid >> 5;
    const int wm   = warp >> 2;
    const int wn   = warp & 3;
    const long bm = (long)blockIdx.y * 128;
    const long bn = (long)blockIdx.x * NT;
    const long KuA = ASP ? K : (K >> 1);
    const long KuB = BSP ? K : (K >> 1);

    float acc[4][NI][4] = {};

    auto issue = [&](int s, int it) {
        unsigned* Sa = sm + s * (ASZ + BSZ);
        unsigned* Sb = Sa + ASZ;
        int row = tid >> 1, half = tid & 1;
        if (ASP) {
            const unsigned* src = A + (bm + row) * KuA + it * 32 + half * 16;
            unsigned* dst = Sa + half * (128 * 16) + row * 16;
            cp16(dst, src); cp16(dst + 4, src + 4);
            cp16(dst + 8, src + 8); cp16(dst + 12, src + 12);
        } else {
            const unsigned* src = A + (bm + row) * KuA + it * 16 + half * 8;
            unsigned* dst = Sa + half * (128 * 8) + row * 8;
            cp16(dst, src); cp16(dst + 4, src + 4);
        }
        if (BSP) {
            const unsigned* sbp = W + (bn + row) * KuB + it * 32 + half * 16;
            unsigned* dbp = Sb + half * (128 * 16) + row * 16;
            cp16(dbp, sbp); cp16(dbp + 4, sbp + 4);
            cp16(dbp + 8, sbp + 8); cp16(dbp + 12, sbp + 12);
        } else {
            const unsigned* sbp = W + (bn + row) * KuB + it * 16 + half * 8;
            unsigned* dbp = Sb + half * (128 * 8) + row * 8;
            cp16(dbp, sbp); cp16(dbp + 4, sbp + 4);
        }
    };

    const int nIter = K >> 5;
    issue(0, 0); CPA_COMMIT;
    issue(1, 1); CPA_COMMIT;

    for (int it = 0; it < nIter; it++) {
        CPA_WAIT1;
        __syncthreads();
        if (it + 2 < nIter) issue((it + 2) % 3, it + 2);
        CPA_COMMIT;

        const unsigned* Sa = sm + (it % 3) * (ASZ + BSZ);
        const unsigned* Sb = Sa + ASZ;

        #pragma unroll
        for (int sc = 0; sc < 2; sc++) {
            const unsigned* Asc = Sa + sc * (128 * RSA);
            const unsigned* Bsc = Sb + sc * (NT * RSB);

            unsigned bhi[NI][2], blo[NI][2];
            #pragma unroll
            for (int ni = 0; ni < NI; ni++) {
                if (BSP) {
                    uint4 f = *reinterpret_cast<const uint4*>(
                        Bsc + (wn * (NT/4) + ni * 8 + gr) * 16 + tc * 4);
                    bhi[ni][0] = f.x; blo[ni][0] = f.y;
                    bhi[ni][1] = f.z; blo[ni][1] = f.w;
                } else {
                    uint2 f = *reinterpret_cast<const uint2*>(
                        Bsc + (wn * (NT/4) + ni * 8 + gr) * 8 + tc * 2);
                    bhi[ni][0] = f.x; bhi[ni][1] = f.y;
                }
            }
            unsigned ahi[4][4], alo[4][4];
            #pragma unroll
            for (int mi = 0; mi < 4; mi++) {
                int r = wm * 64 + mi * 16 + gr;
                if (ASP) {
                    uint4 f0 = *reinterpret_cast<const uint4*>(Asc + r * 16 + tc * 4);
                    uint4 f1 = *reinterpret_cast<const uint4*>(Asc + (r + 8) * 16 + tc * 4);
                    ahi[mi][0] = f0.x; ahi[mi][1] = f1.x; ahi[mi][2] = f0.z; ahi[mi][3] = f1.z;
                    alo[mi][0] = f0.y; alo[mi][1] = f1.y; alo[mi][2] = f0.w; alo[mi][3] = f1.w;
                } else {
                    uint2 f0 = *reinterpret_cast<const uint2*>(Asc + r * 8 + tc * 2);
                    uint2 f1 = *reinterpret_cast<const uint2*>(Asc + (r + 8) * 8 + tc * 2);
                    ahi[mi][0] = f0.x; ahi[mi][1] = f1.x; ahi[mi][2] = f0.y; ahi[mi][3] = f1.y;
                }
            }

            #pragma unroll
            for (int mi = 0; mi < 4; mi++)
                #pragma unroll
                for (int ni = 0; ni < NI; ni++)
                    mma_f16(acc[mi][ni], ahi[mi], bhi[ni]);
            if (ASP) {
                #pragma unroll
                for (int mi = 0; mi < 4; mi++)
                    #pragma unroll
                    for (int ni = 0; ni < NI; ni++)
                        mma_f16(acc[mi][ni], alo[mi], bhi[ni]);
            }
            if (BSP) {
                #pragma unroll
                for (int mi = 0; mi < 4; mi++)
                    #pragma unroll
                    for (int ni = 0; ni < NI; ni++)
                        mma_f16(acc[mi][ni], ahi[mi], blo[ni]);
            }
        }
    }

    // epilogue
    #pragma unroll
    for (int mi = 0; mi < 4; mi++) {
        #pragma unroll
        for (int ni = 0; ni < NI; ni++) {
            long row = bm + wm * 64 + mi * 16 + gr;
            int col = (int)bn + wn * (NT/4) + ni * 8 + tc * 2;
            float* a = acc[mi][ni];
            long i0 = row * (long)N + col;
            long i1 = (row + 8) * (long)N + col;
            if (EPI == 3) {
                long e0i = row * (long)ES + col, e1i = (row + 8) * (long)ES + col;
                float2 e0 = *reinterpret_cast<const float2*>(&E[e0i]);
                float2 e1 = *reinterpret_cast<const float2*>(&E[e1i]);
                uint2 w0 = split2(silu_f(a[0]) * e0.x, silu_f(a[1]) * e0.y);
                uint2 w1 = split2(silu_f(a[2]) * e1.x, silu_f(a[3]) * e1.y);
                int kc = col >> 4, p = (col >> 1) & 7;
                int pos = spos(p);
                *reinterpret_cast<uint2*>(CP + row * (long)N + kc * 16 + pos)       = w0;
                *reinterpret_cast<uint2*>(CP + (row + 8) * (long)N + kc * 16 + pos) = w1;
            } else {
                float2 o0, o1;
                if (EPI == 0) {
                    o0 = make_float2(a[0], a[1]);
                    o1 = make_float2(a[2], a[3]);
                } else if (EPI == 1) {
                    float2 c0 = *reinterpret_cast<float2*>(&C[i0]);
                    float2 c1 = *reinterpret_cast<float2*>(&C[i1]);
                    o0 = make_float2(c0.x + a[0], c0.y + a[1]);
                    o1 = make_float2(c1.x + a[2], c1.y + a[3]);
                } else {
                    long e0i = row * (long)ES + col, e1i = (row + 8) * (long)ES + col;
                    float2 c0 = *reinterpret_cast<float2*>(&C[i0]);
                    float2 c1 = *reinterpret_cast<float2*>(&C[i1]);
                    float2 e0 = *reinterpret_cast<const float2*>(&E[e0i]);
                    float2 e1 = *reinterpret_cast<const float2*>(&E[e1i]);
                    o0 = make_float2(c0.x + a[0]*e0.x, c0.y + a[1]*e0.y);
                    o1 = make_float2(c1.x + a[2]*e1.x, c1.y + a[3]*e1.y);
                }
                *reinterpret_cast<float2*>(&C[i0]) = o0;
                *reinterpret_cast<float2*>(&C[i1]) = o1;
            }
        }
    }
}

// ---------------- decay attention with band pruning; emits packed silu(out) ---------
// Q read from qg buffer with row stride QS
__global__ void __launch_bounds__(256) decay_attn(
    const float* __restrict__ Q, const float* __restrict__ NLv,
    const float* __restrict__ NM, unsigned* __restrict__ AOp, int QS)
{
    const int it = blockIdx.x;
    const int dt = blockIdx.y;
    const int b  = blockIdx.z;
    const float* q  = Q + (long)b*SS*QS + dt*64;
    const float* nl = NLv + (long)b*SS;
    const float* nlmax = NM + b*(SS/64);
    __shared__ float qs[64][64];
    __shared__ float nls[64];
    __shared__ float sgs[64];
    const int tid = threadIdx.x;
    const int tx = tid & 15, ty = tid >> 4;
    float acc[4][4] = {};
    const int i0 = it*64 + ty*4;

    for (int jt = 0; jt <= it; jt++) {
        if (jt < it) {
            float dmin = (float)(it*64 - (jt*64 + 63));
            if (nlmax[jt] * dmin < -25.0f) continue;
        }
        {
            int r = tid >> 4;
            int c = (tid & 15) * 4;
            #pragma unroll
            for (int rr = 0; rr < 64; rr += 16) {
                float4 v = *reinterpret_cast<const float4*>(
                    q + (long)(jt*64 + r + rr) * QS + c);
                *reinterpret_cast<float4*>(&qs[r + rr][c]) = v;
            }
        }
        if (tid < 64) {
            float xv = nl[jt*64 + tid];
            nls[tid] = xv;
            sgs[tid] = expf(xv);
        }
        __syncthreads();

        if (jt < it) {
            #pragma unroll 2
            for (int j = 0; j < 64; j++) {
                float s = sgs[j];
                float w = expf(nls[j] * (float)(i0 - (jt*64 + j)));
                float4 qv = *reinterpret_cast<const float4*>(&qs[j][tx*4]);
                #pragma unroll
                for (int ii = 0; ii < 4; ii++) {
                    acc[ii][0] += w * qv.x;
                    acc[ii][1] += w * qv.y;
                    acc[ii][2] += w * qv.z;
                    acc[ii][3] += w * qv.w;
                    w *= s;
                }
            }
        } else {
            for (int j = 0; j < 64; j++) {
                int jg = jt*64 + j;
                float4 qv = *reinterpret_cast<const float4*>(&qs[j][tx*4]);
                #pragma unroll
                for (int ii = 0; ii < 4; ii++) {
                    int d = i0 + ii - jg;
                    float w = (d >= 0) ? expf(nls[j] * (float)d) : 0.0f;
                    acc[ii][0] += w * qv.x;
                    acc[ii][1] += w * qv.y;
                    acc[ii][2] += w * qv.z;
                    acc[ii][3] += w * qv.w;
                }
            }
        }
        __syncthreads();
    }

    const int kc = dt * 4 + (tx >> 2);
    const int p0 = 2 * (tx & 3);
    const int pos0 = spos(p0), pos1 = spos(p0 + 1);
    #pragma unroll
    for (int ii = 0; ii < 4; ii++) {
        long r = (long)b * SS + i0 + ii;
        uint2 w0 = split2(silu_f(acc[ii][0]), silu_f(acc[ii][1]));
        uint2 w1 = split2(silu_f(acc[ii][2]), silu_f(acc[ii][3]));
        unsigned* base = AOp + r * DIM + kc * 16;
        *reinterpret_cast<uint2*>(base + pos0) = w0;
        *reinterpret_cast<uint2*>(base + pos1) = w1;
    }
}

// ---------------- orchestration ----------------
extern "C" void kernel_launch(void* const* d_in, const int* in_sizes, int n_in,
                              void* d_out, int out_size) {
    const int*   tokens       = (const int*)  d_in[0];
    const float* emb          = (const float*)d_in[1];
    const float* decay_norm_w = (const float*)d_in[2];
    const float* lambda_w     = (const float*)d_in[3];
    const float* quantity_w   = (const float*)d_in[4];
    const float* gate_w       = (const float*)d_in[5];
    const float* output_w     = (const float*)d_in[6];
    const float* ffn_norm_w   = (const float*)d_in[7];
    const float* w_h          = (const float*)d_in[8];
    const float* w_g          = (const float*)d_in[9];
    const float* w_o          = (const float*)d_in[10];
    const float* out_norm_w   = (const float*)d_in[11];
    float* out = (float*)d_out;

    float *x, *qg, *a, *nl, *nm;
    unsigned *h_p, *f_p, *ao_p, *t_p, *hf_p, *emb_p;
    unsigned *wqg_p, *wout_p, *whh_p, *wgg_p, *wo_p;
    cudaGetSymbolAddress((void**)&x,  g_x);
    cudaGetSymbolAddress((void**)&qg, g_qg);
    cudaGetSymbolAddress((void**)&a,  g_a);
    cudaGetSymbolAddress((void**)&nl, g_nl);
    cudaGetSymbolAddress((void**)&nm, g_nlmax);
    cudaGetSymbolAddress((void**)&h_p,  g_h_p);
    cudaGetSymbolAddress((void**)&f_p,  g_f_p);
    cudaGetSymbolAddress((void**)&ao_p, g_ao_p);
    cudaGetSymbolAddress((void**)&t_p,  g_t_p);
    cudaGetSymbolAddress((void**)&hf_p, g_hf_p);
    cudaGetSymbolAddress((void**)&emb_p,g_emb_p);
    cudaGetSymbolAddress((void**)&wqg_p, g_wqg_p);
    cudaGetSymbolAddress((void**)&wout_p,g_wout_p);
    cudaGetSymbolAddress((void**)&whh_p, g_whh_p);
    cudaGetSymbolAddress((void**)&wgg_p, g_wgg_p);
    cudaGetSymbolAddress((void**)&wo_p,  g_wo_p);

    const int SM_11 = 3 * (128*32 + 128*32) * 4;   // 98304
    const int SM_10 = 3 * (128*32 + 128*16) * 4;   // 73728
    const int SM_00 = 3 * (128*16 + 128*16) * 4;   // 49152
    cudaFuncSetAttribute(gemm_tc<1,1,0>, cudaFuncAttributeMaxDynamicSharedMemorySize, SM_11);
    cudaFuncSetAttribute(gemm_tc<1,1,2>, cudaFuncAttributeMaxDynamicSharedMemorySize, SM_11);
    cudaFuncSetAttribute(gemm_tc<1,0,0>, cudaFuncAttributeMaxDynamicSharedMemorySize, SM_10);
    cudaFuncSetAttribute(gemm_tc<1,0,1>, cudaFuncAttributeMaxDynamicSharedMemorySize, SM_10);
    cudaFuncSetAttribute(gemm_tc<1,0,3>, cudaFuncAttributeMaxDynamicSharedMemorySize, SM_10);
    cudaFuncSetAttribute(gemm_tc<0,0,0>, cudaFuncAttributeMaxDynamicSharedMemorySize, SM_00);

    convert_all<<<CB_TOTAL, 256>>>(
        quantity_w, wqg_p, gate_w, output_w, wout_p,
        w_h, whh_p, w_g, wgg_p, w_o, wo_p, emb, emb_p);

    embed_kernel<<<M_TOT * (DIM/4) / 256, 256>>>(tokens, emb, x);

    dim3 gQG (1024/128,  M_TOT/128);   // (8,  32)
    dim3 g512(DIM/128,   M_TOT/128);   // (4,  32)
    dim3 gHID(HID/128,   M_TOT/128);   // (16, 32)
    dim3 gV  (VOCAB/128, M_TOT/128);   // (250,32)
    dim3 gattn(SS/64, DIM/64, BB);

    for (int l = 0; l < NLAYERS; l++) {
        rmsnorm_kernel<true,0><<<M_TOT, 128>>>(x, decay_norm_w + l*DIM,
                                               lambda_w + l*DIM, h_p, nl);
        nlmax_kernel<<<M_TOT/64, 32>>>(nl, nm);
        // [q | g] = h @ [Wq;Wg]^T  (fused, N=1024)
        gemm_tc<1,1,0><<<gQG, 256, SM_11>>>(h_p, wqg_p + (long)l*1024*DIM, qg,
                                            nullptr, nullptr, M_TOT, 1024, DIM, 0);
        decay_attn<<<gattn, 256>>>(qg, nl, nm, ao_p, 1024);
        // x += (silu(ao) @ Wout^T) * g   (E = qg+512, stride 1024)
        gemm_tc<1,1,2><<<g512, 256, SM_11>>>(ao_p, wout_p + (long)l*DIM*DIM, x,
                                             qg + 512, nullptr, M_TOT, DIM, DIM, 1024);
        rmsnorm_kernel<false,0><<<M_TOT, 128>>>(x, ffn_norm_w + l*DIM,
                                                nullptr, f_p, nullptr);
        gemm_tc<1,0,0><<<gHID, 256, SM_10>>>(f_p, whh_p + (long)l*HID*DIM/2, a,
                                             nullptr, nullptr, M_TOT, HID, DIM, 0);
        gemm_tc<1,0,3><<<gHID, 256, SM_10>>>(f_p, wgg_p + (long)l*HID*DIM/2, nullptr,
                                             a, t_p, M_TOT, HID, DIM, HID);
        gemm_tc<1,0,1><<<g512, 256, SM_10>>>(t_p, wo_p + (long)l*DIM*HID/2, x,
                                             nullptr, nullptr, M_TOT, DIM, HID, 0);
    }

    rmsnorm_kernel<false,1><<<M_TOT, 128>>>(x, out_norm_w, nullptr, hf_p, nullptr);
    gemm_tc<0,0,0><<<gV, 256, SM_00>>>(hf_p, emb_p, out, nullptr, nullptr,
                                       M_TOT, VOCAB, DIM, 0);
}